// round 10
// baseline (speedup 1.0000x reference)
#include <cuda_runtime.h>
#include <cuda_bf16.h>
#include <math.h>
#include <float.h>
#include <stdint.h>

// ---------------- problem constants ----------------
#define Bsz   8
#define Npts  2048
#define Kn    16
#define Hc    128
#define Lc    4
#define CDc   128
#define Jtot  (Bsz * Npts * 3)
#define NBlk  (Bsz * Npts)
#define EPSf  1e-12f

typedef __nv_bfloat16 bf16;

// ---------------- scratch ----------------
__device__ int   g_idx[NBlk * Kn];
__device__ float g_M3[Hc * 3];
__device__ bf16  g_UKh[Lc * 256 * 128];
__device__ bf16  g_UKl[Lc * 256 * 128];
__device__ bf16  g_GWh[Lc * 256 * 256];
__device__ bf16  g_GWl[Lc * 256 * 256];
__device__ bf16  g_OWh[128 * 512];
__device__ bf16  g_OWl[128 * 512];
__device__ bf16  g_X0h[Jtot * 128];
__device__ bf16  g_X0l[Jtot * 128];
__device__ bf16  g_X2h[Jtot * 128];
__device__ bf16  g_X2l[Jtot * 128];
__device__ bf16  g_FTh[Jtot * 512];
__device__ bf16  g_FTl[Jtot * 512];
__device__ float g_C[Jtot * 128];            // only the final projection
__device__ float g_gmean[Bsz * 3 * Hc];
__device__ float g_bias[24 * 256];

// ---------------- helpers ----------------
__device__ __forceinline__ void split2(float v, bf16& h, bf16& l) {
    h = __float2bfloat16(v);
    l = __float2bfloat16(v - __bfloat162float(h));
}

__device__ __forceinline__ uint32_t smem_u32(const void* p) {
    uint32_t r;
    asm("{ .reg .u64 t; cvta.to.shared.u64 t, %1; cvt.u32.u64 %0, t; }"
        : "=r"(r) : "l"(p));
    return r;
}

__device__ __forceinline__ void cpasync16(uint32_t dst, const void* src) {
    asm volatile("cp.async.cg.shared.global [%0], [%1], 16;" :: "r"(dst), "l"(src));
}
__device__ __forceinline__ void cpcommit() {
    asm volatile("cp.async.commit_group;" ::: "memory");
}
template <int N> __device__ __forceinline__ void cpwait() {
    asm volatile("cp.async.wait_group %0;" :: "n"(N) : "memory");
}

__device__ __forceinline__ void ldsm_x4(uint32_t& r0, uint32_t& r1,
                                        uint32_t& r2, uint32_t& r3, uint32_t addr) {
    asm volatile("ldmatrix.sync.aligned.m8n8.x4.shared.b16 {%0,%1,%2,%3}, [%4];"
                 : "=r"(r0), "=r"(r1), "=r"(r2), "=r"(r3) : "r"(addr));
}
__device__ __forceinline__ void ldsm_x2(uint32_t& r0, uint32_t& r1, uint32_t addr) {
    asm volatile("ldmatrix.sync.aligned.m8n8.x2.shared.b16 {%0,%1}, [%2];"
                 : "=r"(r0), "=r"(r1) : "r"(addr));
}
__device__ __forceinline__ void mma16816(float* d, const uint32_t* a, const uint32_t* b) {
    asm volatile("mma.sync.aligned.m16n8k16.row.col.f32.bf16.bf16.f32 "
                 "{%0,%1,%2,%3}, {%4,%5,%6,%7}, {%8,%9}, {%0,%1,%2,%3};"
                 : "+f"(d[0]), "+f"(d[1]), "+f"(d[2]), "+f"(d[3])
                 : "r"(a[0]), "r"(a[1]), "r"(a[2]), "r"(a[3]),
                   "r"(b[0]), "r"(b[1]));
}

// ---------------- prep: fused+stacked+split weights ----------------
__global__ void prep_kernel(const float* __restrict__ W_in,
                            const float* __restrict__ Wd_in,
                            const float* __restrict__ Ws,
                            const float* __restrict__ Wds,
                            const float* __restrict__ Gs,
                            const float* __restrict__ Gds,
                            const float* __restrict__ W_out) {
    int t = blockIdx.x * blockDim.x + threadIdx.x;
    const int N3  = Hc * 3;
    const int NUK = Lc * 256 * 128;
    const int NGW = Lc * 256 * 256;
    const int NOW = 128 * 512;
    if (t < N3) {
        int o = t / 3, i = t % 3;
        float s = 0.f;
        #pragma unroll 8
        for (int c = 0; c < Hc; c++) s += Wd_in[o * Hc + c] * W_in[c * 3 + i];
        g_M3[t] = s;
    } else if (t < N3 + NUK) {
        int r = t - N3;
        int l = r >> 15;
        int o = (r >> 7) & 255;
        int c = r & 127;
        float v;
        if (o < 128) {
            v = Ws[l * Hc * Hc + o * Hc + c];
        } else {
            const float* wd = Wds + l * Hc * Hc + (o - 128) * Hc;
            const float* w  = Ws  + l * Hc * Hc;
            float s = 0.f;
            #pragma unroll 8
            for (int cc = 0; cc < Hc; cc++) s += wd[cc] * w[cc * Hc + c];
            v = s;
        }
        split2(v, g_UKh[r], g_UKl[r]);
    } else if (t < N3 + NUK + NGW) {
        int r = t - N3 - NUK;
        int l = r >> 16;
        int o = (r >> 8) & 255;
        int c = r & 255;
        float v;
        if (o < 128) {
            v = Gs[l * Hc * 2 * Hc + o * 2 * Hc + c];
        } else {
            const float* gd = Gds + l * Hc * Hc + (o - 128) * Hc;
            const float* g  = Gs  + l * Hc * 2 * Hc;
            float s = 0.f;
            #pragma unroll 8
            for (int cc = 0; cc < Hc; cc++) s += gd[cc] * g[cc * 2 * Hc + c];
            v = s;
        }
        split2(v, g_GWh[r], g_GWl[r]);
    } else if (t < N3 + NUK + NGW + NOW) {
        int r = t - N3 - NUK - NGW;
        split2(W_out[r], g_OWh[r], g_OWl[r]);
    }
}

// ---------------- kNN ----------------
__global__ void knn_kernel(const float* __restrict__ x) {
    __shared__ float4 spts[Npts];
    int b = blockIdx.x >> 3;
    int chunk = blockIdx.x & 7;
    const float* xb = x + b * 3 * Npts;
    for (int i = threadIdx.x; i < Npts; i += 256) {
        float px = xb[i], py = xb[Npts + i], pz = xb[2 * Npts + i];
        spts[i] = make_float4(px, py, pz, px * px + py * py + pz * pz);
    }
    __syncthreads();
    int q = chunk * 256 + threadIdx.x;
    float4 Q = spts[q];
    float bd[Kn]; int bi[Kn];
    #pragma unroll
    for (int t = 0; t < Kn; t++) { bd[t] = FLT_MAX; bi[t] = 0; }
    float worst = FLT_MAX; int wslot = 0;
    for (int m = 0; m < Npts; m++) {
        float4 P = spts[m];
        float d2 = Q.w + P.w - 2.f * (Q.x * P.x + Q.y * P.y + Q.z * P.z);
        if (d2 < worst) {
            #pragma unroll
            for (int t = 0; t < Kn; t++) if (t == wslot) { bd[t] = d2; bi[t] = m; }
            worst = bd[0]; wslot = 0;
            #pragma unroll
            for (int t = 1; t < Kn; t++) if (bd[t] > worst) { worst = bd[t]; wslot = t; }
        }
    }
    int base = (b * Npts + q) * Kn;
    #pragma unroll
    for (int t = 0; t < Kn; t++) g_idx[base + t] = bi[t];
}

// ---------------- fused edge stage ----------------
__global__ void stage2_kernel(const float* __restrict__ x,
                              const float* __restrict__ W_in) {
    __shared__ float3 snbr[Kn];
    __shared__ float swk[4][Kn];
    int bn = blockIdx.x;
    int b = bn >> 11, n = bn & 2047;
    int c = threadIdx.x;
    int wid = c >> 5, lane = c & 31;
    const float* xb = x + b * 3 * Npts;
    float xnx = xb[n], xny = xb[Npts + n], xnz = xb[2 * Npts + n];
    float xl = sqrtf(xnx * xnx + xny * xny + xnz * xnz);
    float xinv = 1.f / fmaxf(xl, EPSf);
    float dxx = xnx * xinv, dxy = xny * xinv, dxz = xnz * xinv;
    if (c < Kn) {
        int m = g_idx[bn * Kn + c];
        snbr[c] = make_float3(xb[m], xb[Npts + m], xb[2 * Npts + m]);
    }
    __syncthreads();
    float w0 = W_in[c * 3 + 0], w1 = W_in[c * 3 + 1], w2 = W_in[c * 3 + 2];
    float m0 = g_M3[c * 3 + 0], m1 = g_M3[c * 3 + 1], m2 = g_M3[c * 3 + 2];
    float sumk[Kn];
    #pragma unroll
    for (int k = 0; k < Kn; k++) {
        float3 p = snbr[k];
        float c0x = dxy * p.z - dxz * p.y;
        float c0y = dxz * p.x - dxx * p.z;
        float c0z = dxx * p.y - dxy * p.x;
        float e1x = p.x - xnx, e1y = p.y - xny, e1z = p.z - xnz;
        float ux = w0 * c0x + w1 * e1x + w2 * xnx;
        float uy = w0 * c0y + w1 * e1y + w2 * xny;
        float uz = w0 * c0z + w1 * e1z + w2 * xnz;
        sumk[k] = ux * ux + uy * uy + uz * uz;
    }
    #pragma unroll
    for (int o = 16; o > 0; o >>= 1)
        #pragma unroll
        for (int k = 0; k < Kn; k++)
            sumk[k] += __shfl_xor_sync(0xffffffffu, sumk[k], o);
    if (lane == 0) {
        #pragma unroll
        for (int k = 0; k < Kn; k++) swk[wid][k] = sumk[k];
    }
    __syncthreads();
    float ax = 0.f, ay = 0.f, az = 0.f;
    #pragma unroll
    for (int k = 0; k < Kn; k++) {
        float tot = swk[0][k] + swk[1][k] + swk[2][k] + swk[3][k];
        float3 p = snbr[k];
        float c0x = dxy * p.z - dxz * p.y;
        float c0y = dxz * p.x - dxx * p.z;
        float c0z = dxx * p.y - dxy * p.x;
        float e1x = p.x - xnx, e1y = p.y - xny, e1z = p.z - xnz;
        float ux = w0 * c0x + w1 * e1x + w2 * xnx;
        float uy = w0 * c0y + w1 * e1y + w2 * xny;
        float uz = w0 * c0z + w1 * e1z + w2 * xnz;
        float kx = m0 * c0x + m1 * e1x + m2 * xnx;
        float ky = m0 * c0y + m1 * e1y + m2 * xny;
        float kz = m0 * c0z + m1 * e1z + m2 * xnz;
        float s = 1.f / fmaxf(sqrtf(tot), EPSf);
        float kl = sqrtf(kx * kx + ky * ky + kz * kz);
        float ki = 1.f / fmaxf(kl, EPSf);
        kx *= ki; ky *= ki; kz *= ki;
        float dot = s * (ux * kx + uy * ky + uz * kz);
        float neg = fminf(dot, 0.f);
        ax += s * ux - neg * kx;
        ay += s * uy - neg * ky;
        az += s * uz - neg * kz;
    }
    const float invK = 1.f / (float)Kn;
    int j0 = bn * 3;
    split2(ax * invK, g_X0h[(size_t)(j0 + 0) * Hc + c], g_X0l[(size_t)(j0 + 0) * Hc + c]);
    split2(ay * invK, g_X0h[(size_t)(j0 + 1) * Hc + c], g_X0l[(size_t)(j0 + 1) * Hc + c]);
    split2(az * invK, g_X0h[(size_t)(j0 + 2) * Hc + c], g_X0l[(size_t)(j0 + 2) * Hc + c]);
}

// ============ FUSED GEMM + vec_lna pointwise ============
// BM=96 (32 bn triples), BN=256 (U|Kr), BK=32, K'=3*Cin (bf16x3).
// 512 threads = 16 warps (warpM 2 x warpN 8), warp tile 48x32, acc 3x4x4.
// Epilogue: acc(+bias) -> smem fp32 tile -> per-bn Frobenius norm ->
// normalize + VN-activate -> split2 -> dstH/dstL. No fp32 C buffer.
#define PW_SMEM (96 * 260 * 4 + 128)     // 99968 B (>= mainloop 84480 B)

__global__ __launch_bounds__(512, 1)
void gemm_pw(const bf16* __restrict__ Ah, const bf16* __restrict__ Al,
             int lda, int Cin,
             const bf16* __restrict__ Wh, const bf16* __restrict__ Wl, int ldw,
             const float* __restrict__ bias,
             bf16* __restrict__ dstH, bf16* __restrict__ dstL, int ldd, int off) {
    extern __shared__ __align__(16) char smem[];
    int tid = threadIdx.x, lane = tid & 31, wid = tid >> 5;
    int warpM = wid >> 3, warpN = wid & 7;
    int jBase = blockIdx.x * 96;
    float acc[3][4][4];
    #pragma unroll
    for (int mt = 0; mt < 3; mt++)
        #pragma unroll
        for (int nt = 0; nt < 4; nt++)
            #pragma unroll
            for (int e = 0; e < 4; e++) acc[mt][nt][e] = 0.f;

    const int nIter = (3 * Cin) >> 5;
    uint32_t sA0 = smem_u32(smem);               // 3 A bufs @ 7680 B
    uint32_t sB0 = sA0 + 23040;                  // 3 B bufs @ 20480 B

    // 1408 16B chunks per slab: A 96x4, B 256x4
    #define LOAD_SLAB(IT, BUF)                                                   \
    do {                                                                         \
        int k0 = (IT) << 5;                                                      \
        int seg = k0 / Cin;                                                      \
        int kin = k0 - seg * Cin;                                                \
        const bf16* Ap = (seg == 1) ? Al : Ah;                                   \
        const bf16* Bp = (seg == 2) ? Wl : Wh;                                   \
        for (int i = tid; i < 1408; i += 512) {                                  \
            if (i < 384) {                                                       \
                int row = i >> 2, cc = i & 3;                                    \
                cpasync16(sA0 + (BUF) * 7680 + (row * 40 + cc * 8) * 2,          \
                          Ap + (size_t)(jBase + row) * lda + kin + cc * 8);      \
            } else {                                                             \
                int j2 = i - 384;                                                \
                int row = j2 >> 2, cc = j2 & 3;                                  \
                cpasync16(sB0 + (BUF) * 20480 + (row * 40 + cc * 8) * 2,         \
                          Bp + (size_t)row * ldw + kin + cc * 8);                \
            }                                                                    \
        }                                                                        \
    } while (0)

    LOAD_SLAB(0, 0);
    cpcommit();
    LOAD_SLAB(1, 1);
    cpcommit();

    int cur = 0;
    for (int it = 0; it < nIter; it++) {
        if (it == nIter - 1) cpwait<0>(); else cpwait<1>();
        __syncthreads();
        if (it + 2 < nIter) {
            int nbuf = cur + 2; if (nbuf >= 3) nbuf -= 3;
            LOAD_SLAB(it + 2, nbuf);
            cpcommit();
        }
        uint32_t sA = sA0 + cur * 7680;
        uint32_t sB = sB0 + cur * 20480;
        #pragma unroll
        for (int s = 0; s < 2; s++) {
            uint32_t afr[3][4];
            uint32_t bfr[4][2];
            #pragma unroll
            for (int mt = 0; mt < 3; mt++) {
                uint32_t addrA = sA + ((warpM * 48 + mt * 16 + (lane & 15)) * 40) * 2
                               + s * 32 + ((lane >> 4) << 4);
                ldsm_x4(afr[mt][0], afr[mt][1], afr[mt][2], afr[mt][3], addrA);
            }
            #pragma unroll
            for (int nt = 0; nt < 4; nt++) {
                uint32_t addrB = sB + ((warpN * 32 + nt * 8 + (lane & 7)) * 40) * 2
                               + s * 32 + (((lane >> 3) & 1) << 4);
                ldsm_x2(bfr[nt][0], bfr[nt][1], addrB);
            }
            #pragma unroll
            for (int mt = 0; mt < 3; mt++)
                #pragma unroll
                for (int nt = 0; nt < 4; nt++)
                    mma16816(acc[mt][nt], afr[mt], bfr[nt]);
        }
        if (++cur >= 3) cur = 0;
    }
    #undef LOAD_SLAB
    __syncthreads();      // mainloop smem reads done before reuse as fp32 tile

    // ---- epilogue: acc (+bias) -> sC [96][260] fp32 ----
    float* sC = (float*)smem;
    float* stot = sC + 96 * 260;
    #pragma unroll
    for (int mt = 0; mt < 3; mt++) {
        #pragma unroll
        for (int half = 0; half < 2; half++) {
            int row = warpM * 48 + mt * 16 + (lane >> 2) + half * 8;
            int m = jBase + row;
            int bd = (m / 6144) * 3 + (m % 3);
            #pragma unroll
            for (int nt = 0; nt < 4; nt++) {
                int col = warpN * 32 + nt * 8 + (lane & 3) * 2;
                float v0 = acc[mt][nt][half * 2 + 0];
                float v1 = acc[mt][nt][half * 2 + 1];
                if (bias) {
                    v0 += bias[bd * 256 + col];
                    v1 += bias[bd * 256 + col + 1];
                }
                sC[row * 260 + col]     = v0;
                sC[row * 260 + col + 1] = v1;
            }
        }
    }
    __syncthreads();

    // ---- per-bn Frobenius sum over U (cols 0..127, 3 rows) ----
    #pragma unroll
    for (int gi = 0; gi < 2; gi++) {
        int g = wid * 2 + gi;
        float sum = 0.f;
        #pragma unroll
        for (int q = 0; q < 4; q++) {
            int c = lane + q * 32;
            float a0 = sC[(3 * g + 0) * 260 + c];
            float a1 = sC[(3 * g + 1) * 260 + c];
            float a2 = sC[(3 * g + 2) * 260 + c];
            sum += a0 * a0 + a1 * a1 + a2 * a2;
        }
        #pragma unroll
        for (int o = 16; o > 0; o >>= 1) sum += __shfl_xor_sync(0xffffffffu, sum, o);
        if (lane == 0) stot[g] = sum;
    }
    __syncthreads();

    // ---- normalize + VN-activate + split-write ----
    int bnBase = blockIdx.x * 32;
    #pragma unroll
    for (int it2 = 0; it2 < 8; it2++) {
        int item = tid + it2 * 512;
        int g = item >> 7, c = item & 127;
        float s = 1.f / fmaxf(sqrtf(stot[g]), EPSf);
        float ux = sC[(3 * g + 0) * 260 + c];
        float uy = sC[(3 * g + 1) * 260 + c];
        float uz = sC[(3 * g + 2) * 260 + c];
        float kx = sC[(3 * g + 0) * 260 + 128 + c];
        float ky = sC[(3 * g + 1) * 260 + 128 + c];
        float kz = sC[(3 * g + 2) * 260 + 128 + c];
        float kl = sqrtf(kx * kx + ky * ky + kz * kz);
        float ki = 1.f / fmaxf(kl, EPSf);
        kx *= ki; ky *= ki; kz *= ki;
        float dot = s * (ux * kx + uy * ky + uz * kz);
        float neg = fminf(dot, 0.f);
        size_t j0 = (size_t)(bnBase + g) * 3;
        split2(s * ux - neg * kx, dstH[(j0 + 0) * ldd + off + c], dstL[(j0 + 0) * ldd + off + c]);
        split2(s * uy - neg * ky, dstH[(j0 + 1) * ldd + off + c], dstL[(j0 + 1) * ldd + off + c]);
        split2(s * uz - neg * kz, dstH[(j0 + 2) * ldd + off + c], dstL[(j0 + 2) * ldd + off + c]);
    }
}

// ---------------- plain GEMM (final projection only) ----------------
#define GEMM_SMEM 61440
__global__ __launch_bounds__(256, 2)
void gemm_bf16(const bf16* __restrict__ Ah, const bf16* __restrict__ Al, int lda, int Cin,
               const bf16* __restrict__ Wh, const bf16* __restrict__ Wl, int ldw,
               float* __restrict__ C, int ldc) {
    extern __shared__ __align__(16) bf16 smem2[];
    int tid = threadIdx.x, lane = tid & 31, wid = tid >> 5;
    int warpM = wid >> 2, warpN = wid & 3;
    int jBase = blockIdx.x * 128;
    int nBase = blockIdx.y * 128;
    float acc[4][4][4];
    #pragma unroll
    for (int mt = 0; mt < 4; mt++)
        #pragma unroll
        for (int nt = 0; nt < 4; nt++)
            #pragma unroll
            for (int e = 0; e < 4; e++) acc[mt][nt][e] = 0.f;

    const int nIter = (3 * Cin) >> 5;
    const int ar = tid >> 1;
    const int ac = (tid & 1) * 2;
    uint32_t sA0 = smem_u32(smem2);
    uint32_t sB0 = sA0 + 30720;

    #define LOAD_SLAB(IT, BUF)                                                     \
    do {                                                                           \
        int k0 = (IT) << 5;                                                        \
        int seg = k0 / Cin;                                                        \
        int kin = k0 - seg * Cin;                                                  \
        const bf16* Ap = (seg == 1) ? Al : Ah;                                     \
        const bf16* Bp = (seg == 2) ? Wl : Wh;                                     \
        uint32_t adst = sA0 + (BUF) * 10240 + (ar * 40 + ac * 8) * 2;              \
        uint32_t bdst = sB0 + (BUF) * 10240 + (ar * 40 + ac * 8) * 2;              \
        cpasync16(adst,      Ap + (size_t)(jBase + ar) * lda + kin + ac * 8);      \
        cpasync16(adst + 16, Ap + (size_t)(jBase + ar) * lda + kin + ac * 8 + 8);  \
        cpasync16(bdst,      Bp + (size_t)(nBase + ar) * ldw + kin + ac * 8);      \
        cpasync16(bdst + 16, Bp + (size_t)(nBase + ar) * ldw + kin + ac * 8 + 8);  \
    } while (0)

    LOAD_SLAB(0, 0);
    cpcommit();
    LOAD_SLAB(1, 1);
    cpcommit();

    int cur = 0;
    for (int it = 0; it < nIter; it++) {
        if (it == nIter - 1) cpwait<0>(); else cpwait<1>();
        __syncthreads();
        if (it + 2 < nIter) {
            int nbuf = cur + 2; if (nbuf >= 3) nbuf -= 3;
            LOAD_SLAB(it + 2, nbuf);
            cpcommit();
        }
        uint32_t sA = sA0 + cur * 10240;
        uint32_t sB = sB0 + cur * 10240;
        #pragma unroll
        for (int s = 0; s < 2; s++) {
            uint32_t afr[4][4];
            uint32_t bfr[4][2];
            #pragma unroll
            for (int mt = 0; mt < 4; mt++) {
                uint32_t addrA = sA + ((warpM * 64 + mt * 16 + (lane & 15)) * 40) * 2
                               + s * 32 + ((lane >> 4) << 4);
                ldsm_x4(afr[mt][0], afr[mt][1], afr[mt][2], afr[mt][3], addrA);
            }
            #pragma unroll
            for (int nt = 0; nt < 4; nt++) {
                uint32_t addrB = sB + ((warpN * 32 + nt * 8 + (lane & 7)) * 40) * 2
                               + s * 32 + (((lane >> 3) & 1) << 4);
                ldsm_x2(bfr[nt][0], bfr[nt][1], addrB);
            }
            #pragma unroll
            for (int mt = 0; mt < 4; mt++)
                #pragma unroll
                for (int nt = 0; nt < 4; nt++)
                    mma16816(acc[mt][nt], afr[mt], bfr[nt]);
        }
        if (++cur >= 3) cur = 0;
    }
    #undef LOAD_SLAB

    #pragma unroll
    for (int mt = 0; mt < 4; mt++) {
        int m = jBase + warpM * 64 + mt * 16 + (lane >> 2);
        #pragma unroll
        for (int nt = 0; nt < 4; nt++) {
            int n = nBase + warpN * 32 + nt * 8 + (lane & 3) * 2;
            *(float2*)&C[(size_t)m * ldc + n]       = make_float2(acc[mt][nt][0], acc[mt][nt][1]);
            *(float2*)&C[(size_t)(m + 8) * ldc + n] = make_float2(acc[mt][nt][2], acc[mt][nt][3]);
        }
    }
}

// ---------------- fused mean-over-N + g-half bias ----------------
__global__ __launch_bounds__(1024)
void meanN_bias_kernel(const bf16* __restrict__ GWh, const bf16* __restrict__ GWl) {
    __shared__ float part[8][128];
    __shared__ float gm[128];
    int bd = blockIdx.x;
    int b = bd / 3, d = bd % 3;
    int c = threadIdx.x & 127;
    int slab = threadIdx.x >> 7;
    size_t base = ((size_t)(b * Npts + slab * 256) * 3 + d) * 128 + c;
    float s = 0.f;
    #pragma unroll 8
    for (int n = 0; n < 256; n++) {
        size_t a = base + (size_t)n * 384;
        s += __bfloat162float(g_X2h[a]) + __bfloat162float(g_X2l[a]);
    }
    part[slab][c] = s;
    __syncthreads();
    if (threadIdx.x < 128) {
        float t = 0.f;
        #pragma unroll
        for (int p = 0; p < 8; p++) t += part[p][c];
        g_gmean[bd * Hc + c] = t;
        gm[c] = t * (1.f / (float)Npts);
    }
    __syncthreads();
    if (threadIdx.x < 256) {
        int o = threadIdx.x;
        const bf16* rh = GWh + (size_t)o * 256 + 128;
        const bf16* rl = GWl + (size_t)o * 256 + 128;
        float acc = 0.f;
        #pragma unroll 8
        for (int cc = 0; cc < 128; cc++)
            acc += (__bfloat162float(rh[cc]) + __bfloat162float(rl[cc])) * gm[cc];
        g_bias[bd * 256 + o] = acc;
    }
}

// ---------------- coalesced tiled-transpose writeout ----------------
__global__ __launch_bounds__(256)
void writeout_kernel(float* __restrict__ out, int big_off) {
    __shared__ float tile[32][33];
    int tx = threadIdx.x & 31;
    int ty = threadIdx.x >> 5;
    int n0 = blockIdx.x * 32;
    int o0 = blockIdx.y * 32;
    int bd = blockIdx.z;
    int b = bd / 3, d = bd % 3;
    #pragma unroll
    for (int i = 0; i < 4; i++) {
        int n = n0 + ty + i * 8;
        tile[ty + i * 8][tx] = g_C[(((size_t)(b * Npts + n)) * 3 + d) * 128 + o0 + tx];
    }
    __syncthreads();
    #pragma unroll
    for (int i = 0; i < 4; i++) {
        int o = o0 + ty + i * 8;
        out[big_off + (((size_t)(b * 128 + o)) * 3 + d) * Npts + n0 + tx] = tile[tx][ty + i * 8];
    }
}

__global__ void meanout_kernel(float* __restrict__ out, int big_off, int mean_off) {
    int w = blockIdx.x * 8 + (threadIdx.x >> 5);
    int lane = threadIdx.x & 31;
    const float* base = out + big_off + (size_t)w * Npts;
    float s = 0.f;
    #pragma unroll 8
    for (int i = lane; i < Npts; i += 32) s += base[i];
    #pragma unroll
    for (int o = 16; o > 0; o >>= 1) s += __shfl_xor_sync(0xffffffffu, s, o);
    if (lane == 0) out[mean_off + w] = s * (1.f / (float)Npts);
}

// ---------------- host launcher ----------------
extern "C" void kernel_launch(void* const* d_in, const int* in_sizes, int n_in,
                              void* d_out, int out_size) {
    const float* x     = (const float*)d_in[0];
    const float* W_in  = (const float*)d_in[1];
    const float* Wd_in = (const float*)d_in[2];
    const float* Ws    = (const float*)d_in[3];
    const float* Wds   = (const float*)d_in[4];
    const float* Gs    = (const float*)d_in[5];
    const float* Gds   = (const float*)d_in[6];
    const float* W_out = (const float*)d_in[7];
    float* out = (float*)d_out;

    float *pC, *pBias;
    bf16 *pX0h, *pX0l, *pX2h, *pX2l, *pFTh, *pFTl, *pUKh, *pUKl, *pGWh, *pGWl, *pOWh, *pOWl;
    cudaGetSymbolAddress((void**)&pC, g_C);
    cudaGetSymbolAddress((void**)&pBias, g_bias);
    cudaGetSymbolAddress((void**)&pX0h, g_X0h);
    cudaGetSymbolAddress((void**)&pX0l, g_X0l);
    cudaGetSymbolAddress((void**)&pX2h, g_X2h);
    cudaGetSymbolAddress((void**)&pX2l, g_X2l);
    cudaGetSymbolAddress((void**)&pFTh, g_FTh);
    cudaGetSymbolAddress((void**)&pFTl, g_FTl);
    cudaGetSymbolAddress((void**)&pUKh, g_UKh);
    cudaGetSymbolAddress((void**)&pUKl, g_UKl);
    cudaGetSymbolAddress((void**)&pGWh, g_GWh);
    cudaGetSymbolAddress((void**)&pGWl, g_GWl);
    cudaGetSymbolAddress((void**)&pOWh, g_OWh);
    cudaGetSymbolAddress((void**)&pOWl, g_OWl);

    cudaFuncSetAttribute(gemm_pw, cudaFuncAttributeMaxDynamicSharedMemorySize, PW_SMEM);
    cudaFuncSetAttribute(gemm_bf16, cudaFuncAttributeMaxDynamicSharedMemorySize, GEMM_SMEM);

    int mean_off = 0, big_off = 0;
    bool has_mean = true;
    const int BIG = Bsz * CDc * 3 * Npts;
    const int MEAN = Bsz * CDc * 3;
    if (out_size >= BIG + MEAN) { mean_off = 0; big_off = MEAN; }
    else { big_off = 0; has_mean = false; }

    const int prepTot = 384 + Lc * 256 * 128 + Lc * 256 * 256 + 128 * 512;
    prep_kernel<<<(prepTot + 255) / 256, 256>>>(W_in, Wd_in, Ws, Wds, Gs, Gds, W_out);
    knn_kernel<<<Bsz * 8, 256>>>(x);
    stage2_kernel<<<NBlk, 128>>>(x, W_in);

    const bf16* Xh = pX0h;
    const bf16* Xl = pX0l;
    int lda = Hc;
    const int pwGrid = Jtot / 96;                  // 512
    for (int i = 0; i < Lc; i++) {
        gemm_pw<<<pwGrid, 512, PW_SMEM>>>(Xh, Xl, lda, 128,
                    pUKh + (size_t)i * 256 * 128, pUKl + (size_t)i * 256 * 128, 128,
                    nullptr, pX2h, pX2l, 128, 0);
        meanN_bias_kernel<<<24, 1024>>>(pGWh + (size_t)i * 256 * 256,
                                        pGWl + (size_t)i * 256 * 256);
        gemm_pw<<<pwGrid, 512, PW_SMEM>>>(pX2h, pX2l, 128, 128,
                    pGWh + (size_t)i * 256 * 256, pGWl + (size_t)i * 256 * 256, 256,
                    pBias, pFTh, pFTl, 512, i * 128);
        Xh = pFTh + (size_t)i * 128;
        Xl = pFTl + (size_t)i * 128;
        lda = 512;
    }
    gemm_bf16<<<dim3(Jtot / 128, 1), 256, GEMM_SMEM>>>(pFTh, pFTl, 512, 512,
                    pOWh, pOWl, 512, pC, 128);
    writeout_kernel<<<dim3(Npts / 32, 4, 24), 256>>>(out, big_off);
    if (has_mean) meanout_kernel<<<384, 256>>>(out, big_off, mean_off);
}

// round 11
// speedup vs baseline: 1.0612x; 1.0612x over previous
#include <cuda_runtime.h>
#include <cuda_bf16.h>
#include <math.h>
#include <float.h>
#include <stdint.h>

// ---------------- problem constants ----------------
#define Bsz   8
#define Npts  2048
#define Kn    16
#define Hc    128
#define Lc    4
#define CDc   128
#define Jtot  (Bsz * Npts * 3)
#define NBlk  (Bsz * Npts)
#define EPSf  1e-12f
#define FSEG  ((size_t)Jtot * 128)      // one compact layer buffer

typedef __nv_bfloat16 bf16;

// ---------------- scratch ----------------
__device__ int   g_idx[NBlk * Kn];
__device__ float g_M3[Hc * 3];
__device__ bf16  g_UKh[Lc * 256 * 128];
__device__ bf16  g_UKl[Lc * 256 * 128];
__device__ bf16  g_GWh[Lc * 256 * 256];
__device__ bf16  g_GWl[Lc * 256 * 256];
__device__ bf16  g_OWh[128 * 512];
__device__ bf16  g_OWl[128 * 512];
__device__ bf16  g_X0h[Jtot * 128];
__device__ bf16  g_X0l[Jtot * 128];
__device__ bf16  g_X2h[Jtot * 128];
__device__ bf16  g_X2l[Jtot * 128];
__device__ bf16  g_FTh[Lc * Jtot * 128];     // 4 compact per-layer buffers
__device__ bf16  g_FTl[Lc * Jtot * 128];
__device__ float g_C[Jtot * 128];
__device__ float g_gmean[Bsz * 3 * Hc];
__device__ float g_bias[24 * 256];

// ---------------- helpers ----------------
__device__ __forceinline__ void split2(float v, bf16& h, bf16& l) {
    h = __float2bfloat16(v);
    l = __float2bfloat16(v - __bfloat162float(h));
}

__device__ __forceinline__ uint32_t smem_u32(const void* p) {
    uint32_t r;
    asm("{ .reg .u64 t; cvta.to.shared.u64 t, %1; cvt.u32.u64 %0, t; }"
        : "=r"(r) : "l"(p));
    return r;
}

__device__ __forceinline__ void cpasync16(uint32_t dst, const void* src) {
    asm volatile("cp.async.cg.shared.global [%0], [%1], 16;" :: "r"(dst), "l"(src));
}
__device__ __forceinline__ void cpcommit() {
    asm volatile("cp.async.commit_group;" ::: "memory");
}
template <int N> __device__ __forceinline__ void cpwait() {
    asm volatile("cp.async.wait_group %0;" :: "n"(N) : "memory");
}

__device__ __forceinline__ void ldsm_x4(uint32_t& r0, uint32_t& r1,
                                        uint32_t& r2, uint32_t& r3, uint32_t addr) {
    asm volatile("ldmatrix.sync.aligned.m8n8.x4.shared.b16 {%0,%1,%2,%3}, [%4];"
                 : "=r"(r0), "=r"(r1), "=r"(r2), "=r"(r3) : "r"(addr));
}
__device__ __forceinline__ void ldsm_x2(uint32_t& r0, uint32_t& r1, uint32_t addr) {
    asm volatile("ldmatrix.sync.aligned.m8n8.x2.shared.b16 {%0,%1}, [%2];"
                 : "=r"(r0), "=r"(r1) : "r"(addr));
}
__device__ __forceinline__ void mma16816(float* d, const uint32_t* a, const uint32_t* b) {
    asm volatile("mma.sync.aligned.m16n8k16.row.col.f32.bf16.bf16.f32 "
                 "{%0,%1,%2,%3}, {%4,%5,%6,%7}, {%8,%9}, {%0,%1,%2,%3};"
                 : "+f"(d[0]), "+f"(d[1]), "+f"(d[2]), "+f"(d[3])
                 : "r"(a[0]), "r"(a[1]), "r"(a[2]), "r"(a[3]),
                   "r"(b[0]), "r"(b[1]));
}

// ---------------- prep: fused+stacked+split weights ----------------
__global__ void prep_kernel(const float* __restrict__ W_in,
                            const float* __restrict__ Wd_in,
                            const float* __restrict__ Ws,
                            const float* __restrict__ Wds,
                            const float* __restrict__ Gs,
                            const float* __restrict__ Gds,
                            const float* __restrict__ W_out) {
    int t = blockIdx.x * blockDim.x + threadIdx.x;
    const int N3  = Hc * 3;
    const int NUK = Lc * 256 * 128;
    const int NGW = Lc * 256 * 256;
    const int NOW = 128 * 512;
    if (t < N3) {
        int o = t / 3, i = t % 3;
        float s = 0.f;
        #pragma unroll 8
        for (int c = 0; c < Hc; c++) s += Wd_in[o * Hc + c] * W_in[c * 3 + i];
        g_M3[t] = s;
    } else if (t < N3 + NUK) {
        int r = t - N3;
        int l = r >> 15;
        int o = (r >> 7) & 255;
        int c = r & 127;
        float v;
        if (o < 128) {
            v = Ws[l * Hc * Hc + o * Hc + c];
        } else {
            const float* wd = Wds + l * Hc * Hc + (o - 128) * Hc;
            const float* w  = Ws  + l * Hc * Hc;
            float s = 0.f;
            #pragma unroll 8
            for (int cc = 0; cc < Hc; cc++) s += wd[cc] * w[cc * Hc + c];
            v = s;
        }
        split2(v, g_UKh[r], g_UKl[r]);
    } else if (t < N3 + NUK + NGW) {
        int r = t - N3 - NUK;
        int l = r >> 16;
        int o = (r >> 8) & 255;
        int c = r & 255;
        float v;
        if (o < 128) {
            v = Gs[l * Hc * 2 * Hc + o * 2 * Hc + c];
        } else {
            const float* gd = Gds + l * Hc * Hc + (o - 128) * Hc;
            const float* g  = Gs  + l * Hc * 2 * Hc;
            float s = 0.f;
            #pragma unroll 8
            for (int cc = 0; cc < Hc; cc++) s += gd[cc] * g[cc * 2 * Hc + c];
            v = s;
        }
        split2(v, g_GWh[r], g_GWl[r]);
    } else if (t < N3 + NUK + NGW + NOW) {
        int r = t - N3 - NUK - NGW;
        split2(W_out[r], g_OWh[r], g_OWl[r]);
    }
}

// ---------------- kNN (128 blocks x 128 threads) ----------------
__global__ void knn_kernel(const float* __restrict__ x) {
    __shared__ float4 spts[Npts];
    int b = blockIdx.x >> 4;
    int chunk = blockIdx.x & 15;
    const float* xb = x + b * 3 * Npts;
    for (int i = threadIdx.x; i < Npts; i += 128) {
        float px = xb[i], py = xb[Npts + i], pz = xb[2 * Npts + i];
        spts[i] = make_float4(px, py, pz, px * px + py * py + pz * pz);
    }
    __syncthreads();
    int q = chunk * 128 + threadIdx.x;
    float4 Q = spts[q];
    float bd[Kn]; int bi[Kn];
    #pragma unroll
    for (int t = 0; t < Kn; t++) { bd[t] = FLT_MAX; bi[t] = 0; }
    float worst = FLT_MAX; int wslot = 0;
    for (int m = 0; m < Npts; m++) {
        float4 P = spts[m];
        float d2 = Q.w + P.w - 2.f * (Q.x * P.x + Q.y * P.y + Q.z * P.z);
        if (d2 < worst) {
            #pragma unroll
            for (int t = 0; t < Kn; t++) if (t == wslot) { bd[t] = d2; bi[t] = m; }
            worst = bd[0]; wslot = 0;
            #pragma unroll
            for (int t = 1; t < Kn; t++) if (bd[t] > worst) { worst = bd[t]; wslot = t; }
        }
    }
    int base = (b * Npts + q) * Kn;
    #pragma unroll
    for (int t = 0; t < Kn; t++) g_idx[base + t] = bi[t];
}

// ---------------- fused edge stage ----------------
__global__ void stage2_kernel(const float* __restrict__ x,
                              const float* __restrict__ W_in) {
    __shared__ float3 snbr[Kn];
    __shared__ float swk[4][Kn];
    int bn = blockIdx.x;
    int b = bn >> 11, n = bn & 2047;
    int c = threadIdx.x;
    int wid = c >> 5, lane = c & 31;
    const float* xb = x + b * 3 * Npts;
    float xnx = xb[n], xny = xb[Npts + n], xnz = xb[2 * Npts + n];
    float xl = sqrtf(xnx * xnx + xny * xny + xnz * xnz);
    float xinv = 1.f / fmaxf(xl, EPSf);
    float dxx = xnx * xinv, dxy = xny * xinv, dxz = xnz * xinv;
    if (c < Kn) {
        int m = g_idx[bn * Kn + c];
        snbr[c] = make_float3(xb[m], xb[Npts + m], xb[2 * Npts + m]);
    }
    __syncthreads();
    float w0 = W_in[c * 3 + 0], w1 = W_in[c * 3 + 1], w2 = W_in[c * 3 + 2];
    float m0 = g_M3[c * 3 + 0], m1 = g_M3[c * 3 + 1], m2 = g_M3[c * 3 + 2];
    float sumk[Kn];
    #pragma unroll
    for (int k = 0; k < Kn; k++) {
        float3 p = snbr[k];
        float c0x = dxy * p.z - dxz * p.y;
        float c0y = dxz * p.x - dxx * p.z;
        float c0z = dxx * p.y - dxy * p.x;
        float e1x = p.x - xnx, e1y = p.y - xny, e1z = p.z - xnz;
        float ux = w0 * c0x + w1 * e1x + w2 * xnx;
        float uy = w0 * c0y + w1 * e1y + w2 * xny;
        float uz = w0 * c0z + w1 * e1z + w2 * xnz;
        sumk[k] = ux * ux + uy * uy + uz * uz;
    }
    #pragma unroll
    for (int o = 16; o > 0; o >>= 1)
        #pragma unroll
        for (int k = 0; k < Kn; k++)
            sumk[k] += __shfl_xor_sync(0xffffffffu, sumk[k], o);
    if (lane == 0) {
        #pragma unroll
        for (int k = 0; k < Kn; k++) swk[wid][k] = sumk[k];
    }
    __syncthreads();
    float ax = 0.f, ay = 0.f, az = 0.f;
    #pragma unroll
    for (int k = 0; k < Kn; k++) {
        float tot = swk[0][k] + swk[1][k] + swk[2][k] + swk[3][k];
        float3 p = snbr[k];
        float c0x = dxy * p.z - dxz * p.y;
        float c0y = dxz * p.x - dxx * p.z;
        float c0z = dxx * p.y - dxy * p.x;
        float e1x = p.x - xnx, e1y = p.y - xny, e1z = p.z - xnz;
        float ux = w0 * c0x + w1 * e1x + w2 * xnx;
        float uy = w0 * c0y + w1 * e1y + w2 * xny;
        float uz = w0 * c0z + w1 * e1z + w2 * xnz;
        float kx = m0 * c0x + m1 * e1x + m2 * xnx;
        float ky = m0 * c0y + m1 * e1y + m2 * xny;
        float kz = m0 * c0z + m1 * e1z + m2 * xnz;
        float s = 1.f / fmaxf(sqrtf(tot), EPSf);
        float kl = sqrtf(kx * kx + ky * ky + kz * kz);
        float ki = 1.f / fmaxf(kl, EPSf);
        kx *= ki; ky *= ki; kz *= ki;
        float dot = s * (ux * kx + uy * ky + uz * kz);
        float neg = fminf(dot, 0.f);
        ax += s * ux - neg * kx;
        ay += s * uy - neg * ky;
        az += s * uz - neg * kz;
    }
    const float invK = 1.f / (float)Kn;
    int j0 = bn * 3;
    split2(ax * invK, g_X0h[(size_t)(j0 + 0) * Hc + c], g_X0l[(size_t)(j0 + 0) * Hc + c]);
    split2(ay * invK, g_X0h[(size_t)(j0 + 1) * Hc + c], g_X0l[(size_t)(j0 + 1) * Hc + c]);
    split2(az * invK, g_X0h[(size_t)(j0 + 2) * Hc + c], g_X0l[(size_t)(j0 + 2) * Hc + c]);
}

// ============ FUSED GEMM + vec_lna pointwise ============
// BM=96 (32 bn triples), BN=256 (U|Kr), BK=32, K'=3*Cin=384 (Cin=128).
// A compact pitch-128 buffers only.
#define PW_SMEM (96 * 260 * 4 + 128)     // 99968 B

__global__ __launch_bounds__(512, 1)
void gemm_pw(const bf16* __restrict__ Ah, const bf16* __restrict__ Al,
             const bf16* __restrict__ Wh, const bf16* __restrict__ Wl, int ldw,
             const float* __restrict__ bias,
             bf16* __restrict__ dstH, bf16* __restrict__ dstL, int ldd, int off) {
    extern __shared__ __align__(16) char smem[];
    int tid = threadIdx.x, lane = tid & 31, wid = tid >> 5;
    int warpM = wid >> 3, warpN = wid & 7;
    int jBase = blockIdx.x * 96;
    float acc[3][4][4];
    #pragma unroll
    for (int mt = 0; mt < 3; mt++)
        #pragma unroll
        for (int nt = 0; nt < 4; nt++)
            #pragma unroll
            for (int e = 0; e < 4; e++) acc[mt][nt][e] = 0.f;

    const int nIter = 12;                         // 3*128/32
    uint32_t sA0 = smem_u32(smem);
    uint32_t sB0 = sA0 + 23040;

    #define LOAD_SLAB(IT, BUF)                                                   \
    do {                                                                         \
        int k0 = (IT) << 5;                                                      \
        int seg = k0 >> 7;                                                       \
        int kin = k0 & 127;                                                      \
        const bf16* Ap = (seg == 1) ? Al : Ah;                                   \
        const bf16* Bp = (seg == 2) ? Wl : Wh;                                   \
        for (int i = tid; i < 1408; i += 512) {                                  \
            if (i < 384) {                                                       \
                int row = i >> 2, cc = i & 3;                                    \
                cpasync16(sA0 + (BUF) * 7680 + (row * 40 + cc * 8) * 2,          \
                          Ap + (size_t)(jBase + row) * 128 + kin + cc * 8);      \
            } else {                                                             \
                int j2 = i - 384;                                                \
                int row = j2 >> 2, cc = j2 & 3;                                  \
                cpasync16(sB0 + (BUF) * 20480 + (row * 40 + cc * 8) * 2,         \
                          Bp + (size_t)row * ldw + kin + cc * 8);                \
            }                                                                    \
        }                                                                        \
    } while (0)

    LOAD_SLAB(0, 0);
    cpcommit();
    LOAD_SLAB(1, 1);
    cpcommit();

    int cur = 0;
    for (int it = 0; it < nIter; it++) {
        if (it == nIter - 1) cpwait<0>(); else cpwait<1>();
        __syncthreads();
        if (it + 2 < nIter) {
            int nbuf = cur + 2; if (nbuf >= 3) nbuf -= 3;
            LOAD_SLAB(it + 2, nbuf);
            cpcommit();
        }
        uint32_t sA = sA0 + cur * 7680;
        uint32_t sB = sB0 + cur * 20480;
        #pragma unroll
        for (int s = 0; s < 2; s++) {
            uint32_t afr[3][4];
            uint32_t bfr[4][2];
            #pragma unroll
            for (int mt = 0; mt < 3; mt++) {
                uint32_t addrA = sA + ((warpM * 48 + mt * 16 + (lane & 15)) * 40) * 2
                               + s * 32 + ((lane >> 4) << 4);
                ldsm_x4(afr[mt][0], afr[mt][1], afr[mt][2], afr[mt][3], addrA);
            }
            #pragma unroll
            for (int nt = 0; nt < 4; nt++) {
                uint32_t addrB = sB + ((warpN * 32 + nt * 8 + (lane & 7)) * 40) * 2
                               + s * 32 + (((lane >> 3) & 1) << 4);
                ldsm_x2(bfr[nt][0], bfr[nt][1], addrB);
            }
            #pragma unroll
            for (int mt = 0; mt < 3; mt++)
                #pragma unroll
                for (int nt = 0; nt < 4; nt++)
                    mma16816(acc[mt][nt], afr[mt], bfr[nt]);
        }
        if (++cur >= 3) cur = 0;
    }
    #undef LOAD_SLAB
    __syncthreads();

    float* sC = (float*)smem;
    float* stot = sC + 96 * 260;
    #pragma unroll
    for (int mt = 0; mt < 3; mt++) {
        #pragma unroll
        for (int half = 0; half < 2; half++) {
            int row = warpM * 48 + mt * 16 + (lane >> 2) + half * 8;
            int m = jBase + row;
            int bd = (m / 6144) * 3 + (m % 3);
            #pragma unroll
            for (int nt = 0; nt < 4; nt++) {
                int col = warpN * 32 + nt * 8 + (lane & 3) * 2;
                float v0 = acc[mt][nt][half * 2 + 0];
                float v1 = acc[mt][nt][half * 2 + 1];
                if (bias) {
                    v0 += bias[bd * 256 + col];
                    v1 += bias[bd * 256 + col + 1];
                }
                sC[row * 260 + col]     = v0;
                sC[row * 260 + col + 1] = v1;
            }
        }
    }
    __syncthreads();

    #pragma unroll
    for (int gi = 0; gi < 2; gi++) {
        int g = wid * 2 + gi;
        float sum = 0.f;
        #pragma unroll
        for (int q = 0; q < 4; q++) {
            int c = lane + q * 32;
            float a0 = sC[(3 * g + 0) * 260 + c];
            float a1 = sC[(3 * g + 1) * 260 + c];
            float a2 = sC[(3 * g + 2) * 260 + c];
            sum += a0 * a0 + a1 * a1 + a2 * a2;
        }
        #pragma unroll
        for (int o = 16; o > 0; o >>= 1) sum += __shfl_xor_sync(0xffffffffu, sum, o);
        if (lane == 0) stot[g] = sum;
    }
    __syncthreads();

    int bnBase = blockIdx.x * 32;
    #pragma unroll
    for (int it2 = 0; it2 < 8; it2++) {
        int item = tid + it2 * 512;
        int g = item >> 7, c = item & 127;
        float s = 1.f / fmaxf(sqrtf(stot[g]), EPSf);
        float ux = sC[(3 * g + 0) * 260 + c];
        float uy = sC[(3 * g + 1) * 260 + c];
        float uz = sC[(3 * g + 2) * 260 + c];
        float kx = sC[(3 * g + 0) * 260 + 128 + c];
        float ky = sC[(3 * g + 1) * 260 + 128 + c];
        float kz = sC[(3 * g + 2) * 260 + 128 + c];
        float kl = sqrtf(kx * kx + ky * ky + kz * kz);
        float ki = 1.f / fmaxf(kl, EPSf);
        kx *= ki; ky *= ki; kz *= ki;
        float dot = s * (ux * kx + uy * ky + uz * kz);
        float neg = fminf(dot, 0.f);
        size_t j0 = (size_t)(bnBase + g) * 3;
        split2(s * ux - neg * kx, dstH[(j0 + 0) * ldd + off + c], dstL[(j0 + 0) * ldd + off + c]);
        split2(s * uy - neg * ky, dstH[(j0 + 1) * ldd + off + c], dstL[(j0 + 1) * ldd + off + c]);
        split2(s * uz - neg * kz, dstH[(j0 + 2) * ldd + off + c], dstL[(j0 + 2) * ldd + off + c]);
    }
}

// ---------------- final projection GEMM: A = 4 compact layer buffers ----------
// OUT[j][o] = sum over 512 cols (4 layers x 128); K' = 1536, 48 slabs.
#define GEMM_SMEM 61440
__global__ __launch_bounds__(256, 2)
void gemm_final(const bf16* __restrict__ Fh, const bf16* __restrict__ Fl,
                const bf16* __restrict__ Wh, const bf16* __restrict__ Wl,
                float* __restrict__ C) {
    extern __shared__ __align__(16) bf16 smem2[];
    int tid = threadIdx.x, lane = tid & 31, wid = tid >> 5;
    int warpM = wid >> 2, warpN = wid & 3;
    int jBase = blockIdx.x * 128;
    float acc[4][4][4];
    #pragma unroll
    for (int mt = 0; mt < 4; mt++)
        #pragma unroll
        for (int nt = 0; nt < 4; nt++)
            #pragma unroll
            for (int e = 0; e < 4; e++) acc[mt][nt][e] = 0.f;

    const int nIter = 48;
    const int ar = tid >> 1;
    const int ac = (tid & 1) * 2;
    uint32_t sA0 = smem_u32(smem2);
    uint32_t sB0 = sA0 + 30720;

    #define LOAD_SLAB(IT, BUF)                                                     \
    do {                                                                           \
        int k0 = (IT) << 5;                                                        \
        int seg = k0 >> 9;                                                         \
        int kin = k0 & 511;                                                        \
        int layer = kin >> 7;                                                      \
        int kk = kin & 127;                                                        \
        const bf16* Ap = ((seg == 1) ? Fl : Fh) + (size_t)layer * FSEG;            \
        const bf16* Bp = (seg == 2) ? Wl : Wh;                                     \
        uint32_t adst = sA0 + (BUF) * 10240 + (ar * 40 + ac * 8) * 2;              \
        uint32_t bdst = sB0 + (BUF) * 10240 + (ar * 40 + ac * 8) * 2;              \
        cpasync16(adst,      Ap + (size_t)(jBase + ar) * 128 + kk + ac * 8);       \
        cpasync16(adst + 16, Ap + (size_t)(jBase + ar) * 128 + kk + ac * 8 + 8);   \
        cpasync16(bdst,      Bp + (size_t)ar * 512 + kin + ac * 8);                \
        cpasync16(bdst + 16, Bp + (size_t)ar * 512 + kin + ac * 8 + 8);            \
    } while (0)

    LOAD_SLAB(0, 0);
    cpcommit();
    LOAD_SLAB(1, 1);
    cpcommit();

    int cur = 0;
    for (int it = 0; it < nIter; it++) {
        if (it == nIter - 1) cpwait<0>(); else cpwait<1>();
        __syncthreads();
        if (it + 2 < nIter) {
            int nbuf = cur + 2; if (nbuf >= 3) nbuf -= 3;
            LOAD_SLAB(it + 2, nbuf);
            cpcommit();
        }
        uint32_t sA = sA0 + cur * 10240;
        uint32_t sB = sB0 + cur * 10240;
        #pragma unroll
        for (int s = 0; s < 2; s++) {
            uint32_t afr[4][4];
            uint32_t bfr[4][2];
            #pragma unroll
            for (int mt = 0; mt < 4; mt++) {
                uint32_t addrA = sA + ((warpM * 64 + mt * 16 + (lane & 15)) * 40) * 2
                               + s * 32 + ((lane >> 4) << 4);
                ldsm_x4(afr[mt][0], afr[mt][1], afr[mt][2], afr[mt][3], addrA);
            }
            #pragma unroll
            for (int nt = 0; nt < 4; nt++) {
                uint32_t addrB = sB + ((warpN * 32 + nt * 8 + (lane & 7)) * 40) * 2
                               + s * 32 + (((lane >> 3) & 1) << 4);
                ldsm_x2(bfr[nt][0], bfr[nt][1], addrB);
            }
            #pragma unroll
            for (int mt = 0; mt < 4; mt++)
                #pragma unroll
                for (int nt = 0; nt < 4; nt++)
                    mma16816(acc[mt][nt], afr[mt], bfr[nt]);
        }
        if (++cur >= 3) cur = 0;
    }
    #undef LOAD_SLAB

    #pragma unroll
    for (int mt = 0; mt < 4; mt++) {
        int m = jBase + warpM * 64 + mt * 16 + (lane >> 2);
        #pragma unroll
        for (int nt = 0; nt < 4; nt++) {
            int n = warpN * 32 + nt * 8 + (lane & 3) * 2;
            *(float2*)&C[(size_t)m * 128 + n]       = make_float2(acc[mt][nt][0], acc[mt][nt][1]);
            *(float2*)&C[(size_t)(m + 8) * 128 + n] = make_float2(acc[mt][nt][2], acc[mt][nt][3]);
        }
    }
}

// ---------------- fused mean-over-N + g-half bias ----------------
__global__ __launch_bounds__(1024)
void meanN_bias_kernel(const bf16* __restrict__ GWh, const bf16* __restrict__ GWl) {
    __shared__ float part[8][128];
    __shared__ float gm[128];
    int bd = blockIdx.x;
    int b = bd / 3, d = bd % 3;
    int c = threadIdx.x & 127;
    int slab = threadIdx.x >> 7;
    size_t base = ((size_t)(b * Npts + slab * 256) * 3 + d) * 128 + c;
    float s = 0.f;
    #pragma unroll 8
    for (int n = 0; n < 256; n++) {
        size_t a = base + (size_t)n * 384;
        s += __bfloat162float(g_X2h[a]) + __bfloat162float(g_X2l[a]);
    }
    part[slab][c] = s;
    __syncthreads();
    if (threadIdx.x < 128) {
        float t = 0.f;
        #pragma unroll
        for (int p = 0; p < 8; p++) t += part[p][c];
        g_gmean[bd * Hc + c] = t;
        gm[c] = t * (1.f / (float)Npts);
    }
    __syncthreads();
    if (threadIdx.x < 256) {
        int o = threadIdx.x;
        const bf16* rh = GWh + (size_t)o * 256 + 128;
        const bf16* rl = GWl + (size_t)o * 256 + 128;
        float acc = 0.f;
        #pragma unroll 8
        for (int cc = 0; cc < 128; cc++)
            acc += (__bfloat162float(rh[cc]) + __bfloat162float(rl[cc])) * gm[cc];
        g_bias[bd * 256 + o] = acc;
    }
}

// ---------------- coalesced tiled-transpose writeout ----------------
__global__ __launch_bounds__(256)
void writeout_kernel(float* __restrict__ out, int big_off) {
    __shared__ float tile[32][33];
    int tx = threadIdx.x & 31;
    int ty = threadIdx.x >> 5;
    int n0 = blockIdx.x * 32;
    int o0 = blockIdx.y * 32;
    int bd = blockIdx.z;
    int b = bd / 3, d = bd % 3;
    #pragma unroll
    for (int i = 0; i < 4; i++) {
        int n = n0 + ty + i * 8;
        tile[ty + i * 8][tx] = g_C[(((size_t)(b * Npts + n)) * 3 + d) * 128 + o0 + tx];
    }
    __syncthreads();
    #pragma unroll
    for (int i = 0; i < 4; i++) {
        int o = o0 + ty + i * 8;
        out[big_off + (((size_t)(b * 128 + o)) * 3 + d) * Npts + n0 + tx] = tile[tx][ty + i * 8];
    }
}

__global__ void meanout_kernel(float* __restrict__ out, int big_off, int mean_off) {
    int w = blockIdx.x * 8 + (threadIdx.x >> 5);
    int lane = threadIdx.x & 31;
    const float* base = out + big_off + (size_t)w * Npts;
    float s = 0.f;
    #pragma unroll 8
    for (int i = lane; i < Npts; i += 32) s += base[i];
    #pragma unroll
    for (int o = 16; o > 0; o >>= 1) s += __shfl_xor_sync(0xffffffffu, s, o);
    if (lane == 0) out[mean_off + w] = s * (1.f / (float)Npts);
}

// ---------------- host launcher ----------------
extern "C" void kernel_launch(void* const* d_in, const int* in_sizes, int n_in,
                              void* d_out, int out_size) {
    const float* x     = (const float*)d_in[0];
    const float* W_in  = (const float*)d_in[1];
    const float* Wd_in = (const float*)d_in[2];
    const float* Ws    = (const float*)d_in[3];
    const float* Wds   = (const float*)d_in[4];
    const float* Gs    = (const float*)d_in[5];
    const float* Gds   = (const float*)d_in[6];
    const float* W_out = (const float*)d_in[7];
    float* out = (float*)d_out;

    float *pC, *pBias;
    bf16 *pX0h, *pX0l, *pX2h, *pX2l, *pFTh, *pFTl, *pUKh, *pUKl, *pGWh, *pGWl, *pOWh, *pOWl;
    cudaGetSymbolAddress((void**)&pC, g_C);
    cudaGetSymbolAddress((void**)&pBias, g_bias);
    cudaGetSymbolAddress((void**)&pX0h, g_X0h);
    cudaGetSymbolAddress((void**)&pX0l, g_X0l);
    cudaGetSymbolAddress((void**)&pX2h, g_X2h);
    cudaGetSymbolAddress((void**)&pX2l, g_X2l);
    cudaGetSymbolAddress((void**)&pFTh, g_FTh);
    cudaGetSymbolAddress((void**)&pFTl, g_FTl);
    cudaGetSymbolAddress((void**)&pUKh, g_UKh);
    cudaGetSymbolAddress((void**)&pUKl, g_UKl);
    cudaGetSymbolAddress((void**)&pGWh, g_GWh);
    cudaGetSymbolAddress((void**)&pGWl, g_GWl);
    cudaGetSymbolAddress((void**)&pOWh, g_OWh);
    cudaGetSymbolAddress((void**)&pOWl, g_OWl);

    cudaFuncSetAttribute(gemm_pw, cudaFuncAttributeMaxDynamicSharedMemorySize, PW_SMEM);
    cudaFuncSetAttribute(gemm_final, cudaFuncAttributeMaxDynamicSharedMemorySize, GEMM_SMEM);

    int mean_off = 0, big_off = 0;
    bool has_mean = true;
    const int BIG = Bsz * CDc * 3 * Npts;
    const int MEAN = Bsz * CDc * 3;
    if (out_size >= BIG + MEAN) { mean_off = 0; big_off = MEAN; }
    else { big_off = 0; has_mean = false; }

    const int prepTot = 384 + Lc * 256 * 128 + Lc * 256 * 256 + 128 * 512;
    prep_kernel<<<(prepTot + 255) / 256, 256>>>(W_in, Wd_in, Ws, Wds, Gs, Gds, W_out);
    knn_kernel<<<Bsz * 16, 128>>>(x);
    stage2_kernel<<<NBlk, 128>>>(x, W_in);

    const bf16* Xh = pX0h;
    const bf16* Xl = pX0l;
    const int pwGrid = Jtot / 96;                  // 512
    for (int i = 0; i < Lc; i++) {
        gemm_pw<<<pwGrid, 512, PW_SMEM>>>(Xh, Xl,
                    pUKh + (size_t)i * 256 * 128, pUKl + (size_t)i * 256 * 128, 128,
                    nullptr, pX2h, pX2l, 128, 0);
        meanN_bias_kernel<<<24, 1024>>>(pGWh + (size_t)i * 256 * 256,
                                        pGWl + (size_t)i * 256 * 256);
        gemm_pw<<<pwGrid, 512, PW_SMEM>>>(pX2h, pX2l,
                    pGWh + (size_t)i * 256 * 256, pGWl + (size_t)i * 256 * 256, 256,
                    pBias, pFTh + (size_t)i * FSEG, pFTl + (size_t)i * FSEG, 128, 0);
        Xh = pFTh + (size_t)i * FSEG;
        Xl = pFTl + (size_t)i * FSEG;
    }
    gemm_final<<<Jtot / 128, 256, GEMM_SMEM>>>(pFTh, pFTl, pOWh, pOWl, pC);
    writeout_kernel<<<dim3(Npts / 32, 4, 24), 256>>>(out, big_off);
    if (has_mean) meanout_kernel<<<384, 256>>>(out, big_off, mean_off);
}

// round 12
// speedup vs baseline: 1.0824x; 1.0200x over previous
#include <cuda_runtime.h>
#include <cuda_bf16.h>
#include <math.h>
#include <float.h>
#include <stdint.h>

// ---------------- problem constants ----------------
#define Bsz   8
#define Npts  2048
#define Kn    16
#define Hc    128
#define Lc    4
#define CDc   128
#define Jtot  (Bsz * Npts * 3)
#define NBlk  (Bsz * Npts)
#define EPSf  1e-12f
#define FSEG  ((size_t)Jtot * 128)

typedef __nv_bfloat16 bf16;

// ---------------- scratch ----------------
__device__ int   g_idx[NBlk * Kn];
__device__ float g_M3[Hc * 3];
__device__ bf16  g_UKh[Lc * 256 * 128];
__device__ bf16  g_UKl[Lc * 256 * 128];
__device__ bf16  g_GWh[Lc * 256 * 256];
__device__ bf16  g_GWl[Lc * 256 * 256];
__device__ bf16  g_OWh[128 * 512];
__device__ bf16  g_OWl[128 * 512];
__device__ bf16  g_X0h[Jtot * 128];
__device__ bf16  g_X0l[Jtot * 128];
__device__ bf16  g_X2h[Jtot * 128];
__device__ bf16  g_X2l[Jtot * 128];
__device__ bf16  g_FTh[Lc * Jtot * 128];
__device__ bf16  g_FTl[Lc * Jtot * 128];
__device__ float g_gmean[Bsz * 3 * Hc];
__device__ float g_bias[24 * 256];

// ---------------- helpers ----------------
__device__ __forceinline__ void split2(float v, bf16& h, bf16& l) {
    h = __float2bfloat16(v);
    l = __float2bfloat16(v - __bfloat162float(h));
}

__device__ __forceinline__ uint32_t smem_u32(const void* p) {
    uint32_t r;
    asm("{ .reg .u64 t; cvta.to.shared.u64 t, %1; cvt.u32.u64 %0, t; }"
        : "=r"(r) : "l"(p));
    return r;
}

__device__ __forceinline__ void cpasync16(uint32_t dst, const void* src) {
    asm volatile("cp.async.cg.shared.global [%0], [%1], 16;" :: "r"(dst), "l"(src));
}
__device__ __forceinline__ void cpcommit() {
    asm volatile("cp.async.commit_group;" ::: "memory");
}
template <int N> __device__ __forceinline__ void cpwait() {
    asm volatile("cp.async.wait_group %0;" :: "n"(N) : "memory");
}

__device__ __forceinline__ void ldsm_x4(uint32_t& r0, uint32_t& r1,
                                        uint32_t& r2, uint32_t& r3, uint32_t addr) {
    asm volatile("ldmatrix.sync.aligned.m8n8.x4.shared.b16 {%0,%1,%2,%3}, [%4];"
                 : "=r"(r0), "=r"(r1), "=r"(r2), "=r"(r3) : "r"(addr));
}
__device__ __forceinline__ void ldsm_x2(uint32_t& r0, uint32_t& r1, uint32_t addr) {
    asm volatile("ldmatrix.sync.aligned.m8n8.x2.shared.b16 {%0,%1}, [%2];"
                 : "=r"(r0), "=r"(r1) : "r"(addr));
}
__device__ __forceinline__ void mma16816(float* d, const uint32_t* a, const uint32_t* b) {
    asm volatile("mma.sync.aligned.m16n8k16.row.col.f32.bf16.bf16.f32 "
                 "{%0,%1,%2,%3}, {%4,%5,%6,%7}, {%8,%9}, {%0,%1,%2,%3};"
                 : "+f"(d[0]), "+f"(d[1]), "+f"(d[2]), "+f"(d[3])
                 : "r"(a[0]), "r"(a[1]), "r"(a[2]), "r"(a[3]),
                   "r"(b[0]), "r"(b[1]));
}

// ---------------- prep: fused+stacked+split weights ----------------
__global__ void prep_kernel(const float* __restrict__ W_in,
                            const float* __restrict__ Wd_in,
                            const float* __restrict__ Ws,
                            const float* __restrict__ Wds,
                            const float* __restrict__ Gs,
                            const float* __restrict__ Gds,
                            const float* __restrict__ W_out) {
    int t = blockIdx.x * blockDim.x + threadIdx.x;
    const int N3  = Hc * 3;
    const int NUK = Lc * 256 * 128;
    const int NGW = Lc * 256 * 256;
    const int NOW = 128 * 512;
    if (t < N3) {
        int o = t / 3, i = t % 3;
        float s = 0.f;
        #pragma unroll 8
        for (int c = 0; c < Hc; c++) s += Wd_in[o * Hc + c] * W_in[c * 3 + i];
        g_M3[t] = s;
    } else if (t < N3 + NUK) {
        int r = t - N3;
        int l = r >> 15;
        int o = (r >> 7) & 255;
        int c = r & 127;
        float v;
        if (o < 128) {
            v = Ws[l * Hc * Hc + o * Hc + c];
        } else {
            const float* wd = Wds + l * Hc * Hc + (o - 128) * Hc;
            const float* w  = Ws  + l * Hc * Hc;
            float s = 0.f;
            #pragma unroll 8
            for (int cc = 0; cc < Hc; cc++) s += wd[cc] * w[cc * Hc + c];
            v = s;
        }
        split2(v, g_UKh[r], g_UKl[r]);
    } else if (t < N3 + NUK + NGW) {
        int r = t - N3 - NUK;
        int l = r >> 16;
        int o = (r >> 8) & 255;
        int c = r & 255;
        float v;
        if (o < 128) {
            v = Gs[l * Hc * 2 * Hc + o * 2 * Hc + c];
        } else {
            const float* gd = Gds + l * Hc * Hc + (o - 128) * Hc;
            const float* g  = Gs  + l * Hc * 2 * Hc;
            float s = 0.f;
            #pragma unroll 8
            for (int cc = 0; cc < Hc; cc++) s += gd[cc] * g[cc * 2 * Hc + c];
            v = s;
        }
        split2(v, g_GWh[r], g_GWl[r]);
    } else if (t < N3 + NUK + NGW + NOW) {
        int r = t - N3 - NUK - NGW;
        split2(W_out[r], g_OWh[r], g_OWl[r]);
    }
}

// ---------------- kNN ----------------
__global__ void knn_kernel(const float* __restrict__ x) {
    __shared__ float4 spts[Npts];
    int b = blockIdx.x >> 4;
    int chunk = blockIdx.x & 15;
    const float* xb = x + b * 3 * Npts;
    for (int i = threadIdx.x; i < Npts; i += 128) {
        float px = xb[i], py = xb[Npts + i], pz = xb[2 * Npts + i];
        spts[i] = make_float4(px, py, pz, px * px + py * py + pz * pz);
    }
    __syncthreads();
    int q = chunk * 128 + threadIdx.x;
    float4 Q = spts[q];
    float bd[Kn]; int bi[Kn];
    #pragma unroll
    for (int t = 0; t < Kn; t++) { bd[t] = FLT_MAX; bi[t] = 0; }
    float worst = FLT_MAX; int wslot = 0;
    for (int m = 0; m < Npts; m++) {
        float4 P = spts[m];
        float d2 = Q.w + P.w - 2.f * (Q.x * P.x + Q.y * P.y + Q.z * P.z);
        if (d2 < worst) {
            #pragma unroll
            for (int t = 0; t < Kn; t++) if (t == wslot) { bd[t] = d2; bi[t] = m; }
            worst = bd[0]; wslot = 0;
            #pragma unroll
            for (int t = 1; t < Kn; t++) if (bd[t] > worst) { worst = bd[t]; wslot = t; }
        }
    }
    int base = (b * Npts + q) * Kn;
    #pragma unroll
    for (int t = 0; t < Kn; t++) g_idx[base + t] = bi[t];
}

// ---------------- fused edge stage ----------------
__global__ void stage2_kernel(const float* __restrict__ x,
                              const float* __restrict__ W_in) {
    __shared__ float3 snbr[Kn];
    __shared__ float swk[4][Kn];
    int bn = blockIdx.x;
    int b = bn >> 11, n = bn & 2047;
    int c = threadIdx.x;
    int wid = c >> 5, lane = c & 31;
    const float* xb = x + b * 3 * Npts;
    float xnx = xb[n], xny = xb[Npts + n], xnz = xb[2 * Npts + n];
    float xl = sqrtf(xnx * xnx + xny * xny + xnz * xnz);
    float xinv = 1.f / fmaxf(xl, EPSf);
    float dxx = xnx * xinv, dxy = xny * xinv, dxz = xnz * xinv;
    if (c < Kn) {
        int m = g_idx[bn * Kn + c];
        snbr[c] = make_float3(xb[m], xb[Npts + m], xb[2 * Npts + m]);
    }
    __syncthreads();
    float w0 = W_in[c * 3 + 0], w1 = W_in[c * 3 + 1], w2 = W_in[c * 3 + 2];
    float m0 = g_M3[c * 3 + 0], m1 = g_M3[c * 3 + 1], m2 = g_M3[c * 3 + 2];
    float sumk[Kn];
    #pragma unroll
    for (int k = 0; k < Kn; k++) {
        float3 p = snbr[k];
        float c0x = dxy * p.z - dxz * p.y;
        float c0y = dxz * p.x - dxx * p.z;
        float c0z = dxx * p.y - dxy * p.x;
        float e1x = p.x - xnx, e1y = p.y - xny, e1z = p.z - xnz;
        float ux = w0 * c0x + w1 * e1x + w2 * xnx;
        float uy = w0 * c0y + w1 * e1y + w2 * xny;
        float uz = w0 * c0z + w1 * e1z + w2 * xnz;
        sumk[k] = ux * ux + uy * uy + uz * uz;
    }
    #pragma unroll
    for (int o = 16; o > 0; o >>= 1)
        #pragma unroll
        for (int k = 0; k < Kn; k++)
            sumk[k] += __shfl_xor_sync(0xffffffffu, sumk[k], o);
    if (lane == 0) {
        #pragma unroll
        for (int k = 0; k < Kn; k++) swk[wid][k] = sumk[k];
    }
    __syncthreads();
    float ax = 0.f, ay = 0.f, az = 0.f;
    #pragma unroll
    for (int k = 0; k < Kn; k++) {
        float tot = swk[0][k] + swk[1][k] + swk[2][k] + swk[3][k];
        float3 p = snbr[k];
        float c0x = dxy * p.z - dxz * p.y;
        float c0y = dxz * p.x - dxx * p.z;
        float c0z = dxx * p.y - dxy * p.x;
        float e1x = p.x - xnx, e1y = p.y - xny, e1z = p.z - xnz;
        float ux = w0 * c0x + w1 * e1x + w2 * xnx;
        float uy = w0 * c0y + w1 * e1y + w2 * xny;
        float uz = w0 * c0z + w1 * e1z + w2 * xnz;
        float kx = m0 * c0x + m1 * e1x + m2 * xnx;
        float ky = m0 * c0y + m1 * e1y + m2 * xny;
        float kz = m0 * c0z + m1 * e1z + m2 * xnz;
        float s = 1.f / fmaxf(sqrtf(tot), EPSf);
        float kl = sqrtf(kx * kx + ky * ky + kz * kz);
        float ki = 1.f / fmaxf(kl, EPSf);
        kx *= ki; ky *= ki; kz *= ki;
        float dot = s * (ux * kx + uy * ky + uz * kz);
        float neg = fminf(dot, 0.f);
        ax += s * ux - neg * kx;
        ay += s * uy - neg * ky;
        az += s * uz - neg * kz;
    }
    const float invK = 1.f / (float)Kn;
    int j0 = bn * 3;
    split2(ax * invK, g_X0h[(size_t)(j0 + 0) * Hc + c], g_X0l[(size_t)(j0 + 0) * Hc + c]);
    split2(ay * invK, g_X0h[(size_t)(j0 + 1) * Hc + c], g_X0l[(size_t)(j0 + 1) * Hc + c]);
    split2(az * invK, g_X0h[(size_t)(j0 + 2) * Hc + c], g_X0l[(size_t)(j0 + 2) * Hc + c]);
}

// ============ FUSED GEMM + vec_lna pointwise (layer GEMMs) ============
#define PW_SMEM (96 * 260 * 4 + 128)

__global__ __launch_bounds__(512, 1)
void gemm_pw(const bf16* __restrict__ Ah, const bf16* __restrict__ Al,
             const bf16* __restrict__ Wh, const bf16* __restrict__ Wl, int ldw,
             const float* __restrict__ bias,
             bf16* __restrict__ dstH, bf16* __restrict__ dstL, int ldd, int off) {
    extern __shared__ __align__(16) char smem[];
    int tid = threadIdx.x, lane = tid & 31, wid = tid >> 5;
    int warpM = wid >> 3, warpN = wid & 7;
    int jBase = blockIdx.x * 96;
    float acc[3][4][4];
    #pragma unroll
    for (int mt = 0; mt < 3; mt++)
        #pragma unroll
        for (int nt = 0; nt < 4; nt++)
            #pragma unroll
            for (int e = 0; e < 4; e++) acc[mt][nt][e] = 0.f;

    const int nIter = 12;
    uint32_t sA0 = smem_u32(smem);
    uint32_t sB0 = sA0 + 23040;

    #define LOAD_SLAB(IT, BUF)                                                   \
    do {                                                                         \
        int k0 = (IT) << 5;                                                      \
        int seg = k0 >> 7;                                                       \
        int kin = k0 & 127;                                                      \
        const bf16* Ap = (seg == 1) ? Al : Ah;                                   \
        const bf16* Bp = (seg == 2) ? Wl : Wh;                                   \
        for (int i = tid; i < 1408; i += 512) {                                  \
            if (i < 384) {                                                       \
                int row = i >> 2, cc = i & 3;                                    \
                cpasync16(sA0 + (BUF) * 7680 + (row * 40 + cc * 8) * 2,          \
                          Ap + (size_t)(jBase + row) * 128 + kin + cc * 8);      \
            } else {                                                             \
                int j2 = i - 384;                                                \
                int row = j2 >> 2, cc = j2 & 3;                                  \
                cpasync16(sB0 + (BUF) * 20480 + (row * 40 + cc * 8) * 2,         \
                          Bp + (size_t)row * ldw + kin + cc * 8);                \
            }                                                                    \
        }                                                                        \
    } while (0)

    LOAD_SLAB(0, 0);
    cpcommit();
    LOAD_SLAB(1, 1);
    cpcommit();

    int cur = 0;
    for (int it = 0; it < nIter; it++) {
        if (it == nIter - 1) cpwait<0>(); else cpwait<1>();
        __syncthreads();
        if (it + 2 < nIter) {
            int nbuf = cur + 2; if (nbuf >= 3) nbuf -= 3;
            LOAD_SLAB(it + 2, nbuf);
            cpcommit();
        }
        uint32_t sA = sA0 + cur * 7680;
        uint32_t sB = sB0 + cur * 20480;
        #pragma unroll
        for (int s = 0; s < 2; s++) {
            uint32_t afr[3][4];
            uint32_t bfr[4][2];
            #pragma unroll
            for (int mt = 0; mt < 3; mt++) {
                uint32_t addrA = sA + ((warpM * 48 + mt * 16 + (lane & 15)) * 40) * 2
                               + s * 32 + ((lane >> 4) << 4);
                ldsm_x4(afr[mt][0], afr[mt][1], afr[mt][2], afr[mt][3], addrA);
            }
            #pragma unroll
            for (int nt = 0; nt < 4; nt++) {
                uint32_t addrB = sB + ((warpN * 32 + nt * 8 + (lane & 7)) * 40) * 2
                               + s * 32 + (((lane >> 3) & 1) << 4);
                ldsm_x2(bfr[nt][0], bfr[nt][1], addrB);
            }
            #pragma unroll
            for (int mt = 0; mt < 3; mt++)
                #pragma unroll
                for (int nt = 0; nt < 4; nt++)
                    mma16816(acc[mt][nt], afr[mt], bfr[nt]);
        }
        if (++cur >= 3) cur = 0;
    }
    #undef LOAD_SLAB
    __syncthreads();

    float* sC = (float*)smem;
    float* stot = sC + 96 * 260;
    #pragma unroll
    for (int mt = 0; mt < 3; mt++) {
        #pragma unroll
        for (int half = 0; half < 2; half++) {
            int row = warpM * 48 + mt * 16 + (lane >> 2) + half * 8;
            int m = jBase + row;
            int bd = (m / 6144) * 3 + (m % 3);
            #pragma unroll
            for (int nt = 0; nt < 4; nt++) {
                int col = warpN * 32 + nt * 8 + (lane & 3) * 2;
                float v0 = acc[mt][nt][half * 2 + 0];
                float v1 = acc[mt][nt][half * 2 + 1];
                if (bias) {
                    v0 += bias[bd * 256 + col];
                    v1 += bias[bd * 256 + col + 1];
                }
                sC[row * 260 + col]     = v0;
                sC[row * 260 + col + 1] = v1;
            }
        }
    }
    __syncthreads();

    #pragma unroll
    for (int gi = 0; gi < 2; gi++) {
        int g = wid * 2 + gi;
        float sum = 0.f;
        #pragma unroll
        for (int q = 0; q < 4; q++) {
            int c = lane + q * 32;
            float a0 = sC[(3 * g + 0) * 260 + c];
            float a1 = sC[(3 * g + 1) * 260 + c];
            float a2 = sC[(3 * g + 2) * 260 + c];
            sum += a0 * a0 + a1 * a1 + a2 * a2;
        }
        #pragma unroll
        for (int o = 16; o > 0; o >>= 1) sum += __shfl_xor_sync(0xffffffffu, sum, o);
        if (lane == 0) stot[g] = sum;
    }
    __syncthreads();

    int bnBase = blockIdx.x * 32;
    #pragma unroll
    for (int it2 = 0; it2 < 8; it2++) {
        int item = tid + it2 * 512;
        int g = item >> 7, c = item & 127;
        float s = 1.f / fmaxf(sqrtf(stot[g]), EPSf);
        float ux = sC[(3 * g + 0) * 260 + c];
        float uy = sC[(3 * g + 1) * 260 + c];
        float uz = sC[(3 * g + 2) * 260 + c];
        float kx = sC[(3 * g + 0) * 260 + 128 + c];
        float ky = sC[(3 * g + 1) * 260 + 128 + c];
        float kz = sC[(3 * g + 2) * 260 + 128 + c];
        float kl = sqrtf(kx * kx + ky * ky + kz * kz);
        float ki = 1.f / fmaxf(kl, EPSf);
        kx *= ki; ky *= ki; kz *= ki;
        float dot = s * (ux * kx + uy * ky + uz * kz);
        float neg = fminf(dot, 0.f);
        size_t j0 = (size_t)(bnBase + g) * 3;
        split2(s * ux - neg * kx, dstH[(j0 + 0) * ldd + off + c], dstL[(j0 + 0) * ldd + off + c]);
        split2(s * uy - neg * ky, dstH[(j0 + 1) * ldd + off + c], dstL[(j0 + 1) * ldd + off + c]);
        split2(s * uz - neg * kz, dstH[(j0 + 2) * ldd + off + c], dstL[(j0 + 2) * ldd + off + c]);
    }
}

// ---------------- final projection: read-A-once 3-pass + fused transpose out --
// BM=96 (32 bn triples), BN=128, 16 K-slabs of 32 cols. Per slab: load
// Ah/Al/Wh/Wl, run (Ah,Wh),(Ah,Wl),(Al,Wh). Epilogue writes out directly.
// smem: Ah[2]@0(7680 ea), Al[2]@15360, Wh[2]@30720(10240 ea), Wl[2]@51200. 71680 B.
#define GF_SMEM 71680

__global__ __launch_bounds__(256, 2)
void gemm_final(const bf16* __restrict__ Fh, const bf16* __restrict__ Fl,
                const bf16* __restrict__ Wh, const bf16* __restrict__ Wl,
                float* __restrict__ out, int big_off) {
    extern __shared__ __align__(16) char smemf[];
    int tid = threadIdx.x, lane = tid & 31, wid = tid >> 5;
    int warpM = wid >> 2, warpN = wid & 3;
    int jBase = blockIdx.x * 96;
    float acc[3][4][4];
    #pragma unroll
    for (int mt = 0; mt < 3; mt++)
        #pragma unroll
        for (int nt = 0; nt < 4; nt++)
            #pragma unroll
            for (int e = 0; e < 4; e++) acc[mt][nt][e] = 0.f;

    uint32_t sb = smem_u32(smemf);

    #define LOAD_SLAB(KIN, BUF)                                                  \
    do {                                                                         \
        int layer = (KIN) >> 2;                                                  \
        int kk0 = ((KIN) & 3) * 32;                                              \
        const bf16* FhL = Fh + (size_t)layer * FSEG;                             \
        const bf16* FlL = Fl + (size_t)layer * FSEG;                             \
        int kw0 = (KIN) * 32;                                                    \
        for (int i = tid; i < 1792; i += 256) {                                  \
            if (i < 384) {                                                       \
                int row = i >> 2, cc = i & 3;                                    \
                cpasync16(sb + (BUF) * 7680 + (row * 40 + cc * 8) * 2,           \
                          FhL + (size_t)(jBase + row) * 128 + kk0 + cc * 8);     \
            } else if (i < 768) {                                                \
                int r2 = i - 384;                                                \
                int row = r2 >> 2, cc = r2 & 3;                                  \
                cpasync16(sb + 15360 + (BUF) * 7680 + (row * 40 + cc * 8) * 2,   \
                          FlL + (size_t)(jBase + row) * 128 + kk0 + cc * 8);     \
            } else if (i < 1280) {                                               \
                int r2 = i - 768;                                                \
                int row = r2 >> 2, cc = r2 & 3;                                  \
                cpasync16(sb + 30720 + (BUF) * 10240 + (row * 40 + cc * 8) * 2,  \
                          Wh + (size_t)row * 512 + kw0 + cc * 8);                \
            } else {                                                             \
                int r2 = i - 1280;                                               \
                int row = r2 >> 2, cc = r2 & 3;                                  \
                cpasync16(sb + 51200 + (BUF) * 10240 + (row * 40 + cc * 8) * 2,  \
                          Wl + (size_t)row * 512 + kw0 + cc * 8);                \
            }                                                                    \
        }                                                                        \
    } while (0)

    LOAD_SLAB(0, 0);
    cpcommit();
    cpwait<0>();
    __syncthreads();

    for (int kin = 0; kin < 16; kin++) {
        int cur = kin & 1;
        if (kin + 1 < 16) {
            LOAD_SLAB(kin + 1, cur ^ 1);
            cpcommit();
        }
        uint32_t sAh = sb + cur * 7680;
        uint32_t sAl = sb + 15360 + cur * 7680;
        uint32_t sWh = sb + 30720 + cur * 10240;
        uint32_t sWl = sb + 51200 + cur * 10240;
        #pragma unroll
        for (int pass = 0; pass < 3; pass++) {
            uint32_t sA = (pass == 2) ? sAl : sAh;
            uint32_t sB = (pass == 1) ? sWl : sWh;
            #pragma unroll
            for (int s = 0; s < 2; s++) {
                uint32_t afr[3][4];
                uint32_t bfr[4][2];
                #pragma unroll
                for (int mt = 0; mt < 3; mt++) {
                    uint32_t addrA = sA + ((warpM * 48 + mt * 16 + (lane & 15)) * 40) * 2
                                   + s * 32 + ((lane >> 4) << 4);
                    ldsm_x4(afr[mt][0], afr[mt][1], afr[mt][2], afr[mt][3], addrA);
                }
                #pragma unroll
                for (int nt = 0; nt < 4; nt++) {
                    uint32_t addrB = sB + ((warpN * 32 + nt * 8 + (lane & 7)) * 40) * 2
                                   + s * 32 + (((lane >> 3) & 1) << 4);
                    ldsm_x2(bfr[nt][0], bfr[nt][1], addrB);
                }
                #pragma unroll
                for (int mt = 0; mt < 3; mt++)
                    #pragma unroll
                    for (int nt = 0; nt < 4; nt++)
                        mma16816(acc[mt][nt], afr[mt], bfr[nt]);
            }
        }
        if (kin + 1 < 16) {
            cpwait<0>();
        }
        __syncthreads();
    }
    #undef LOAD_SLAB

    // epilogue: acc -> smem [96][133] fp32 -> transposed write to out
    float* sC = (float*)smemf;
    #pragma unroll
    for (int mt = 0; mt < 3; mt++) {
        #pragma unroll
        for (int half = 0; half < 2; half++) {
            int row = warpM * 48 + mt * 16 + (lane >> 2) + half * 8;
            #pragma unroll
            for (int nt = 0; nt < 4; nt++) {
                int col = warpN * 32 + nt * 8 + (lane & 3) * 2;
                sC[row * 133 + col]     = acc[mt][nt][half * 2 + 0];
                sC[row * 133 + col + 1] = acc[mt][nt][half * 2 + 1];
            }
        }
    }
    __syncthreads();

    int b = jBase / 6144;
    int nB = (jBase % 6144) / 3;
    for (int item = tid; item < 12288; item += 256) {
        int g = item & 31;
        int dcol = item >> 5;        // o*3 + d
        int d = dcol % 3, o = dcol / 3;
        out[big_off + (((size_t)(b * 128 + o)) * 3 + d) * Npts + nB + g]
            = sC[(g * 3 + d) * 133 + o];
    }
}

// ---------------- fused mean-over-N + g-half bias ----------------
__global__ __launch_bounds__(1024)
void meanN_bias_kernel(const bf16* __restrict__ GWh, const bf16* __restrict__ GWl) {
    __shared__ float part[8][128];
    __shared__ float gm[128];
    int bd = blockIdx.x;
    int b = bd / 3, d = bd % 3;
    int c = threadIdx.x & 127;
    int slab = threadIdx.x >> 7;
    size_t base = ((size_t)(b * Npts + slab * 256) * 3 + d) * 128 + c;
    float s = 0.f;
    #pragma unroll 8
    for (int n = 0; n < 256; n++) {
        size_t a = base + (size_t)n * 384;
        s += __bfloat162float(g_X2h[a]) + __bfloat162float(g_X2l[a]);
    }
    part[slab][c] = s;
    __syncthreads();
    if (threadIdx.x < 128) {
        float t = 0.f;
        #pragma unroll
        for (int p = 0; p < 8; p++) t += part[p][c];
        g_gmean[bd * Hc + c] = t;
        gm[c] = t * (1.f / (float)Npts);
    }
    __syncthreads();
    if (threadIdx.x < 256) {
        int o = threadIdx.x;
        const bf16* rh = GWh + (size_t)o * 256 + 128;
        const bf16* rl = GWl + (size_t)o * 256 + 128;
        float acc = 0.f;
        #pragma unroll 8
        for (int cc = 0; cc < 128; cc++)
            acc += (__bfloat162float(rh[cc]) + __bfloat162float(rl[cc])) * gm[cc];
        g_bias[bd * 256 + o] = acc;
    }
}

__global__ void meanout_kernel(float* __restrict__ out, int big_off, int mean_off) {
    int w = blockIdx.x * 8 + (threadIdx.x >> 5);
    int lane = threadIdx.x & 31;
    const float* base = out + big_off + (size_t)w * Npts;
    float s = 0.f;
    #pragma unroll 8
    for (int i = lane; i < Npts; i += 32) s += base[i];
    #pragma unroll
    for (int o = 16; o > 0; o >>= 1) s += __shfl_xor_sync(0xffffffffu, s, o);
    if (lane == 0) out[mean_off + w] = s * (1.f / (float)Npts);
}

// ---------------- host launcher ----------------
extern "C" void kernel_launch(void* const* d_in, const int* in_sizes, int n_in,
                              void* d_out, int out_size) {
    const float* x     = (const float*)d_in[0];
    const float* W_in  = (const float*)d_in[1];
    const float* Wd_in = (const float*)d_in[2];
    const float* Ws    = (const float*)d_in[3];
    const float* Wds   = (const float*)d_in[4];
    const float* Gs    = (const float*)d_in[5];
    const float* Gds   = (const float*)d_in[6];
    const float* W_out = (const float*)d_in[7];
    float* out = (float*)d_out;

    float *pBias;
    bf16 *pX0h, *pX0l, *pX2h, *pX2l, *pFTh, *pFTl, *pUKh, *pUKl, *pGWh, *pGWl, *pOWh, *pOWl;
    cudaGetSymbolAddress((void**)&pBias, g_bias);
    cudaGetSymbolAddress((void**)&pX0h, g_X0h);
    cudaGetSymbolAddress((void**)&pX0l, g_X0l);
    cudaGetSymbolAddress((void**)&pX2h, g_X2h);
    cudaGetSymbolAddress((void**)&pX2l, g_X2l);
    cudaGetSymbolAddress((void**)&pFTh, g_FTh);
    cudaGetSymbolAddress((void**)&pFTl, g_FTl);
    cudaGetSymbolAddress((void**)&pUKh, g_UKh);
    cudaGetSymbolAddress((void**)&pUKl, g_UKl);
    cudaGetSymbolAddress((void**)&pGWh, g_GWh);
    cudaGetSymbolAddress((void**)&pGWl, g_GWl);
    cudaGetSymbolAddress((void**)&pOWh, g_OWh);
    cudaGetSymbolAddress((void**)&pOWl, g_OWl);

    cudaFuncSetAttribute(gemm_pw, cudaFuncAttributeMaxDynamicSharedMemorySize, PW_SMEM);
    cudaFuncSetAttribute(gemm_final, cudaFuncAttributeMaxDynamicSharedMemorySize, GF_SMEM);

    int mean_off = 0, big_off = 0;
    bool has_mean = true;
    const int BIG = Bsz * CDc * 3 * Npts;
    const int MEAN = Bsz * CDc * 3;
    if (out_size >= BIG + MEAN) { mean_off = 0; big_off = MEAN; }
    else { big_off = 0; has_mean = false; }

    const int prepTot = 384 + Lc * 256 * 128 + Lc * 256 * 256 + 128 * 512;
    prep_kernel<<<(prepTot + 255) / 256, 256>>>(W_in, Wd_in, Ws, Wds, Gs, Gds, W_out);
    knn_kernel<<<Bsz * 16, 128>>>(x);
    stage2_kernel<<<NBlk, 128>>>(x, W_in);

    const bf16* Xh = pX0h;
    const bf16* Xl = pX0l;
    const int pwGrid = Jtot / 96;                  // 512
    for (int i = 0; i < Lc; i++) {
        gemm_pw<<<pwGrid, 512, PW_SMEM>>>(Xh, Xl,
                    pUKh + (size_t)i * 256 * 128, pUKl + (size_t)i * 256 * 128, 128,
                    nullptr, pX2h, pX2l, 128, 0);
        meanN_bias_kernel<<<24, 1024>>>(pGWh + (size_t)i * 256 * 256,
                                        pGWl + (size_t)i * 256 * 256);
        gemm_pw<<<pwGrid, 512, PW_SMEM>>>(pX2h, pX2l,
                    pGWh + (size_t)i * 256 * 256, pGWl + (size_t)i * 256 * 256, 256,
                    pBias, pFTh + (size_t)i * FSEG, pFTl + (size_t)i * FSEG, 128, 0);
        Xh = pFTh + (size_t)i * FSEG;
        Xl = pFTl + (size_t)i * FSEG;
    }
    gemm_final<<<Jtot / 96, 256, GF_SMEM>>>(pFTh, pFTl, pOWh, pOWl, out, big_off);
    if (has_mean) meanout_kernel<<<384, 256>>>(out, big_off, mean_off);
}

// round 13
// speedup vs baseline: 1.1537x; 1.0659x over previous
#include <cuda_runtime.h>
#include <cuda_bf16.h>
#include <math.h>
#include <float.h>
#include <stdint.h>

// ---------------- problem constants ----------------
#define Bsz   8
#define Npts  2048
#define Kn    16
#define Hc    128
#define Lc    4
#define CDc   128
#define Jtot  (Bsz * Npts * 3)
#define NBlk  (Bsz * Npts)
#define EPSf  1e-12f
#define FSEG  ((size_t)Jtot * 128)

typedef __nv_bfloat16 bf16;

// ---------------- scratch ----------------
__device__ int   g_idx[NBlk * Kn];
__device__ float g_M3[Hc * 3];
__device__ float g_G[9];                     // W_in^T W_in
__device__ bf16  g_UKh[Lc * 256 * 128];
__device__ bf16  g_UKl[Lc * 256 * 128];
__device__ bf16  g_GWh[Lc * 256 * 256];
__device__ bf16  g_GWl[Lc * 256 * 256];
__device__ bf16  g_OWh[128 * 512];
__device__ bf16  g_OWl[128 * 512];
__device__ bf16  g_X0h[Jtot * 128];
__device__ bf16  g_X0l[Jtot * 128];
__device__ bf16  g_X2h[Jtot * 128];
__device__ bf16  g_X2l[Jtot * 128];
__device__ bf16  g_FTh[Lc * Jtot * 128];
__device__ bf16  g_FTl[Lc * Jtot * 128];
__device__ float g_gmean[Bsz * 3 * Hc];
__device__ float g_bias[24 * 256];
__device__ float g_pmean[512 * 384];         // per-CTA h1 partial sums
__device__ float g_opart[512 * 384];         // per-CTA output partial sums

// ---------------- helpers ----------------
__device__ __forceinline__ void split2(float v, bf16& h, bf16& l) {
    h = __float2bfloat16(v);
    l = __float2bfloat16(v - __bfloat162float(h));
}

__device__ __forceinline__ uint32_t smem_u32(const void* p) {
    uint32_t r;
    asm("{ .reg .u64 t; cvta.to.shared.u64 t, %1; cvt.u32.u64 %0, t; }"
        : "=r"(r) : "l"(p));
    return r;
}

__device__ __forceinline__ void cpasync16(uint32_t dst, const void* src) {
    asm volatile("cp.async.cg.shared.global [%0], [%1], 16;" :: "r"(dst), "l"(src));
}
__device__ __forceinline__ void cpcommit() {
    asm volatile("cp.async.commit_group;" ::: "memory");
}
template <int N> __device__ __forceinline__ void cpwait() {
    asm volatile("cp.async.wait_group %0;" :: "n"(N) : "memory");
}

__device__ __forceinline__ void ldsm_x4(uint32_t& r0, uint32_t& r1,
                                        uint32_t& r2, uint32_t& r3, uint32_t addr) {
    asm volatile("ldmatrix.sync.aligned.m8n8.x4.shared.b16 {%0,%1,%2,%3}, [%4];"
                 : "=r"(r0), "=r"(r1), "=r"(r2), "=r"(r3) : "r"(addr));
}
__device__ __forceinline__ void ldsm_x2(uint32_t& r0, uint32_t& r1, uint32_t addr) {
    asm volatile("ldmatrix.sync.aligned.m8n8.x2.shared.b16 {%0,%1}, [%2];"
                 : "=r"(r0), "=r"(r1) : "r"(addr));
}
__device__ __forceinline__ void mma16816(float* d, const uint32_t* a, const uint32_t* b) {
    asm volatile("mma.sync.aligned.m16n8k16.row.col.f32.bf16.bf16.f32 "
                 "{%0,%1,%2,%3}, {%4,%5,%6,%7}, {%8,%9}, {%0,%1,%2,%3};"
                 : "+f"(d[0]), "+f"(d[1]), "+f"(d[2]), "+f"(d[3])
                 : "r"(a[0]), "r"(a[1]), "r"(a[2]), "r"(a[3]),
                   "r"(b[0]), "r"(b[1]));
}

// ---------------- prep: fused+stacked+split weights + G ----------------
__global__ void prep_kernel(const float* __restrict__ W_in,
                            const float* __restrict__ Wd_in,
                            const float* __restrict__ Ws,
                            const float* __restrict__ Wds,
                            const float* __restrict__ Gs,
                            const float* __restrict__ Gds,
                            const float* __restrict__ W_out) {
    int t = blockIdx.x * blockDim.x + threadIdx.x;
    const int N3  = Hc * 3;
    const int NG  = 9;
    const int NUK = Lc * 256 * 128;
    const int NGW = Lc * 256 * 256;
    const int NOW = 128 * 512;
    if (t < N3) {
        int o = t / 3, i = t % 3;
        float s = 0.f;
        #pragma unroll 8
        for (int c = 0; c < Hc; c++) s += Wd_in[o * Hc + c] * W_in[c * 3 + i];
        g_M3[t] = s;
    } else if (t < N3 + NG) {
        int r = t - N3;
        int i = r / 3, j = r % 3;
        float s = 0.f;
        #pragma unroll 8
        for (int c = 0; c < Hc; c++) s += W_in[c * 3 + i] * W_in[c * 3 + j];
        g_G[r] = s;
    } else if (t < N3 + NG + NUK) {
        int r = t - N3 - NG;
        int l = r >> 15;
        int o = (r >> 7) & 255;
        int c = r & 127;
        float v;
        if (o < 128) {
            v = Ws[l * Hc * Hc + o * Hc + c];
        } else {
            const float* wd = Wds + l * Hc * Hc + (o - 128) * Hc;
            const float* w  = Ws  + l * Hc * Hc;
            float s = 0.f;
            #pragma unroll 8
            for (int cc = 0; cc < Hc; cc++) s += wd[cc] * w[cc * Hc + c];
            v = s;
        }
        split2(v, g_UKh[r], g_UKl[r]);
    } else if (t < N3 + NG + NUK + NGW) {
        int r = t - N3 - NG - NUK;
        int l = r >> 16;
        int o = (r >> 8) & 255;
        int c = r & 255;
        float v;
        if (o < 128) {
            v = Gs[l * Hc * 2 * Hc + o * 2 * Hc + c];
        } else {
            const float* gd = Gds + l * Hc * Hc + (o - 128) * Hc;
            const float* g  = Gs  + l * Hc * 2 * Hc;
            float s = 0.f;
            #pragma unroll 8
            for (int cc = 0; cc < Hc; cc++) s += gd[cc] * g[cc * 2 * Hc + c];
            v = s;
        }
        split2(v, g_GWh[r], g_GWl[r]);
    } else if (t < N3 + NG + NUK + NGW + NOW) {
        int r = t - N3 - NG - NUK - NGW;
        split2(W_out[r], g_OWh[r], g_OWl[r]);
    }
}

// ---------------- kNN ----------------
__global__ void knn_kernel(const float* __restrict__ x) {
    __shared__ float4 spts[Npts];
    int b = blockIdx.x >> 4;
    int chunk = blockIdx.x & 15;
    const float* xb = x + b * 3 * Npts;
    for (int i = threadIdx.x; i < Npts; i += 128) {
        float px = xb[i], py = xb[Npts + i], pz = xb[2 * Npts + i];
        spts[i] = make_float4(px, py, pz, px * px + py * py + pz * pz);
    }
    __syncthreads();
    int q = chunk * 128 + threadIdx.x;
    float4 Q = spts[q];
    float bd[Kn]; int bi[Kn];
    #pragma unroll
    for (int t = 0; t < Kn; t++) { bd[t] = FLT_MAX; bi[t] = 0; }
    float worst = FLT_MAX; int wslot = 0;
    for (int m = 0; m < Npts; m++) {
        float4 P = spts[m];
        float d2 = Q.w + P.w - 2.f * (Q.x * P.x + Q.y * P.y + Q.z * P.z);
        if (d2 < worst) {
            #pragma unroll
            for (int t = 0; t < Kn; t++) if (t == wslot) { bd[t] = d2; bi[t] = m; }
            worst = bd[0]; wslot = 0;
            #pragma unroll
            for (int t = 1; t < Kn; t++) if (bd[t] > worst) { worst = bd[t]; wslot = t; }
        }
    }
    int base = (b * Npts + q) * Kn;
    #pragma unroll
    for (int t = 0; t < Kn; t++) g_idx[base + t] = bi[t];
}

// ---------------- edge stage: single pass via quadratic-form norm ----------
// tot = G00|cross|^2 + G11|e1|^2 + G22|x|^2 + 2 G12 (e1.x)
// (cross is orthogonal to both x and nbr, so G01/G02 terms vanish)
__global__ void stage2_kernel(const float* __restrict__ x,
                              const float* __restrict__ W_in) {
    __shared__ float3 snbr[Kn];
    int bn = blockIdx.x;
    int b = bn >> 11, n = bn & 2047;
    int c = threadIdx.x;
    const float* xb = x + b * 3 * Npts;
    float xnx = xb[n], xny = xb[Npts + n], xnz = xb[2 * Npts + n];
    float xx = xnx * xnx + xny * xny + xnz * xnz;
    float xl = sqrtf(xx);
    float xinv = 1.f / fmaxf(xl, EPSf);
    float dxx = xnx * xinv, dxy = xny * xinv, dxz = xnz * xinv;
    if (c < Kn) {
        int m = g_idx[bn * Kn + c];
        snbr[c] = make_float3(xb[m], xb[Npts + m], xb[2 * Npts + m]);
    }
    __syncthreads();
    float w0 = W_in[c * 3 + 0], w1 = W_in[c * 3 + 1], w2 = W_in[c * 3 + 2];
    float m0 = g_M3[c * 3 + 0], m1 = g_M3[c * 3 + 1], m2 = g_M3[c * 3 + 2];
    float G00 = g_G[0], G11 = g_G[4], G12 = g_G[5];
    float q22 = g_G[8] * xx;
    float ax = 0.f, ay = 0.f, az = 0.f;
    #pragma unroll
    for (int k = 0; k < Kn; k++) {
        float3 p = snbr[k];
        float c0x = dxy * p.z - dxz * p.y;
        float c0y = dxz * p.x - dxx * p.z;
        float c0z = dxx * p.y - dxy * p.x;
        float e1x = p.x - xnx, e1y = p.y - xny, e1z = p.z - xnz;
        float cc2 = c0x * c0x + c0y * c0y + c0z * c0z;
        float ee2 = e1x * e1x + e1y * e1y + e1z * e1z;
        float exd = e1x * xnx + e1y * xny + e1z * xnz;
        float tot = G00 * cc2 + G11 * ee2 + q22 + 2.f * G12 * exd;
        float s = 1.f / fmaxf(sqrtf(tot), EPSf);
        float ux = w0 * c0x + w1 * e1x + w2 * xnx;
        float uy = w0 * c0y + w1 * e1y + w2 * xny;
        float uz = w0 * c0z + w1 * e1z + w2 * xnz;
        float kx = m0 * c0x + m1 * e1x + m2 * xnx;
        float ky = m0 * c0y + m1 * e1y + m2 * xny;
        float kz = m0 * c0z + m1 * e1z + m2 * xnz;
        float kl = sqrtf(kx * kx + ky * ky + kz * kz);
        float ki = 1.f / fmaxf(kl, EPSf);
        kx *= ki; ky *= ki; kz *= ki;
        float dot = s * (ux * kx + uy * ky + uz * kz);
        float neg = fminf(dot, 0.f);
        ax += s * ux - neg * kx;
        ay += s * uy - neg * ky;
        az += s * uz - neg * kz;
    }
    const float invK = 1.f / (float)Kn;
    int j0 = bn * 3;
    split2(ax * invK, g_X0h[(size_t)(j0 + 0) * Hc + c], g_X0l[(size_t)(j0 + 0) * Hc + c]);
    split2(ay * invK, g_X0h[(size_t)(j0 + 1) * Hc + c], g_X0l[(size_t)(j0 + 1) * Hc + c]);
    split2(az * invK, g_X0h[(size_t)(j0 + 2) * Hc + c], g_X0l[(size_t)(j0 + 2) * Hc + c]);
}

// ============ FUSED GEMM + vec_lna pointwise (layer GEMMs) ============
#define PW_SMEM (96 * 260 * 4 + 128)

__global__ __launch_bounds__(512, 1)
void gemm_pw(const bf16* __restrict__ Ah, const bf16* __restrict__ Al,
             const bf16* __restrict__ Wh, const bf16* __restrict__ Wl, int ldw,
             const float* __restrict__ bias,
             bf16* __restrict__ dstH, bf16* __restrict__ dstL, int ldd, int off,
             float* __restrict__ pmean) {
    extern __shared__ __align__(16) char smem[];
    int tid = threadIdx.x, lane = tid & 31, wid = tid >> 5;
    int warpM = wid >> 3, warpN = wid & 7;
    int jBase = blockIdx.x * 96;
    float acc[3][4][4];
    #pragma unroll
    for (int mt = 0; mt < 3; mt++)
        #pragma unroll
        for (int nt = 0; nt < 4; nt++)
            #pragma unroll
            for (int e = 0; e < 4; e++) acc[mt][nt][e] = 0.f;

    const int nIter = 12;
    uint32_t sA0 = smem_u32(smem);
    uint32_t sB0 = sA0 + 23040;

    #define LOAD_SLAB(IT, BUF)                                                   \
    do {                                                                         \
        int k0 = (IT) << 5;                                                      \
        int seg = k0 >> 7;                                                       \
        int kin = k0 & 127;                                                      \
        const bf16* Ap = (seg == 1) ? Al : Ah;                                   \
        const bf16* Bp = (seg == 2) ? Wl : Wh;                                   \
        for (int i = tid; i < 1408; i += 512) {                                  \
            if (i < 384) {                                                       \
                int row = i >> 2, cc = i & 3;                                    \
                cpasync16(sA0 + (BUF) * 7680 + (row * 40 + cc * 8) * 2,          \
                          Ap + (size_t)(jBase + row) * 128 + kin + cc * 8);      \
            } else {                                                             \
                int j2 = i - 384;                                                \
                int row = j2 >> 2, cc = j2 & 3;                                  \
                cpasync16(sB0 + (BUF) * 20480 + (row * 40 + cc * 8) * 2,         \
                          Bp + (size_t)row * ldw + kin + cc * 8);                \
            }                                                                    \
        }                                                                        \
    } while (0)

    LOAD_SLAB(0, 0);
    cpcommit();
    LOAD_SLAB(1, 1);
    cpcommit();

    int cur = 0;
    for (int it = 0; it < nIter; it++) {
        if (it == nIter - 1) cpwait<0>(); else cpwait<1>();
        __syncthreads();
        if (it + 2 < nIter) {
            int nbuf = cur + 2; if (nbuf >= 3) nbuf -= 3;
            LOAD_SLAB(it + 2, nbuf);
            cpcommit();
        }
        uint32_t sA = sA0 + cur * 7680;
        uint32_t sB = sB0 + cur * 20480;
        #pragma unroll
        for (int s = 0; s < 2; s++) {
            uint32_t afr[3][4];
            uint32_t bfr[4][2];
            #pragma unroll
            for (int mt = 0; mt < 3; mt++) {
                uint32_t addrA = sA + ((warpM * 48 + mt * 16 + (lane & 15)) * 40) * 2
                               + s * 32 + ((lane >> 4) << 4);
                ldsm_x4(afr[mt][0], afr[mt][1], afr[mt][2], afr[mt][3], addrA);
            }
            #pragma unroll
            for (int nt = 0; nt < 4; nt++) {
                uint32_t addrB = sB + ((warpN * 32 + nt * 8 + (lane & 7)) * 40) * 2
                               + s * 32 + (((lane >> 3) & 1) << 4);
                ldsm_x2(bfr[nt][0], bfr[nt][1], addrB);
            }
            #pragma unroll
            for (int mt = 0; mt < 3; mt++)
                #pragma unroll
                for (int nt = 0; nt < 4; nt++)
                    mma16816(acc[mt][nt], afr[mt], bfr[nt]);
        }
        if (++cur >= 3) cur = 0;
    }
    #undef LOAD_SLAB
    __syncthreads();

    float* sC = (float*)smem;
    float* stot = sC + 96 * 260;
    #pragma unroll
    for (int mt = 0; mt < 3; mt++) {
        #pragma unroll
        for (int half = 0; half < 2; half++) {
            int row = warpM * 48 + mt * 16 + (lane >> 2) + half * 8;
            int m = jBase + row;
            int bd = (m / 6144) * 3 + (m % 3);
            #pragma unroll
            for (int nt = 0; nt < 4; nt++) {
                int col = warpN * 32 + nt * 8 + (lane & 3) * 2;
                float v0 = acc[mt][nt][half * 2 + 0];
                float v1 = acc[mt][nt][half * 2 + 1];
                if (bias) {
                    v0 += bias[bd * 256 + col];
                    v1 += bias[bd * 256 + col + 1];
                }
                sC[row * 260 + col]     = v0;
                sC[row * 260 + col + 1] = v1;
            }
        }
    }
    __syncthreads();

    #pragma unroll
    for (int gi = 0; gi < 2; gi++) {
        int g = wid * 2 + gi;
        float sum = 0.f;
        #pragma unroll
        for (int q = 0; q < 4; q++) {
            int c = lane + q * 32;
            float a0 = sC[(3 * g + 0) * 260 + c];
            float a1 = sC[(3 * g + 1) * 260 + c];
            float a2 = sC[(3 * g + 2) * 260 + c];
            sum += a0 * a0 + a1 * a1 + a2 * a2;
        }
        #pragma unroll
        for (int o = 16; o > 0; o >>= 1) sum += __shfl_xor_sync(0xffffffffu, sum, o);
        if (lane == 0) stot[g] = sum;
    }
    __syncthreads();

    int bnBase = blockIdx.x * 32;
    float ls0 = 0.f, ls1 = 0.f, ls2 = 0.f;
    #pragma unroll
    for (int it2 = 0; it2 < 8; it2++) {
        int item = tid + it2 * 512;
        int g = item >> 7, c = item & 127;
        float s = 1.f / fmaxf(sqrtf(stot[g]), EPSf);
        float ux = sC[(3 * g + 0) * 260 + c];
        float uy = sC[(3 * g + 1) * 260 + c];
        float uz = sC[(3 * g + 2) * 260 + c];
        float kx = sC[(3 * g + 0) * 260 + 128 + c];
        float ky = sC[(3 * g + 1) * 260 + 128 + c];
        float kz = sC[(3 * g + 2) * 260 + 128 + c];
        float kl = sqrtf(kx * kx + ky * ky + kz * kz);
        float ki = 1.f / fmaxf(kl, EPSf);
        kx *= ki; ky *= ki; kz *= ki;
        float dot = s * (ux * kx + uy * ky + uz * kz);
        float neg = fminf(dot, 0.f);
        float v0 = s * ux - neg * kx;
        float v1 = s * uy - neg * ky;
        float v2 = s * uz - neg * kz;
        size_t j0 = (size_t)(bnBase + g) * 3;
        split2(v0, dstH[(j0 + 0) * ldd + off + c], dstL[(j0 + 0) * ldd + off + c]);
        split2(v1, dstH[(j0 + 1) * ldd + off + c], dstL[(j0 + 1) * ldd + off + c]);
        split2(v2, dstH[(j0 + 2) * ldd + off + c], dstL[(j0 + 2) * ldd + off + c]);
        ls0 += v0; ls1 += v1; ls2 += v2;
    }

    // per-CTA h1 partial sum (only for UK calls feeding the layer mean)
    if (pmean) {
        __syncthreads();
        float* sp = sC;                    // reuse: 512 x 3 floats
        sp[tid * 3 + 0] = ls0;
        sp[tid * 3 + 1] = ls1;
        sp[tid * 3 + 2] = ls2;
        __syncthreads();
        if (tid < 384) {
            int d = tid >> 7, c = tid & 127;
            float s4 = sp[(0 * 128 + c) * 3 + d] + sp[(1 * 128 + c) * 3 + d]
                     + sp[(2 * 128 + c) * 3 + d] + sp[(3 * 128 + c) * 3 + d];
            pmean[blockIdx.x * 384 + d * 128 + c] = s4;
        }
    }
}

// ---------------- final projection + output-mean partials ----------------
#define GF_SMEM 71680

__global__ __launch_bounds__(256, 2)
void gemm_final(const bf16* __restrict__ Fh, const bf16* __restrict__ Fl,
                const bf16* __restrict__ Wh, const bf16* __restrict__ Wl,
                float* __restrict__ out, int big_off) {
    extern __shared__ __align__(16) char smemf[];
    int tid = threadIdx.x, lane = tid & 31, wid = tid >> 5;
    int warpM = wid >> 2, warpN = wid & 3;
    int jBase = blockIdx.x * 96;
    float acc[3][4][4];
    #pragma unroll
    for (int mt = 0; mt < 3; mt++)
        #pragma unroll
        for (int nt = 0; nt < 4; nt++)
            #pragma unroll
            for (int e = 0; e < 4; e++) acc[mt][nt][e] = 0.f;

    uint32_t sb = smem_u32(smemf);

    #define LOAD_SLAB(KIN, BUF)                                                  \
    do {                                                                         \
        int layer = (KIN) >> 2;                                                  \
        int kk0 = ((KIN) & 3) * 32;                                              \
        const bf16* FhL = Fh + (size_t)layer * FSEG;                             \
        const bf16* FlL = Fl + (size_t)layer * FSEG;                             \
        int kw0 = (KIN) * 32;                                                    \
        for (int i = tid; i < 1792; i += 256) {                                  \
            if (i < 384) {                                                       \
                int row = i >> 2, cc = i & 3;                                    \
                cpasync16(sb + (BUF) * 7680 + (row * 40 + cc * 8) * 2,           \
                          FhL + (size_t)(jBase + row) * 128 + kk0 + cc * 8);     \
            } else if (i < 768) {                                                \
                int r2 = i - 384;                                                \
                int row = r2 >> 2, cc = r2 & 3;                                  \
                cpasync16(sb + 15360 + (BUF) * 7680 + (row * 40 + cc * 8) * 2,   \
                          FlL + (size_t)(jBase + row) * 128 + kk0 + cc * 8);     \
            } else if (i < 1280) {                                               \
                int r2 = i - 768;                                                \
                int row = r2 >> 2, cc = r2 & 3;                                  \
                cpasync16(sb + 30720 + (BUF) * 10240 + (row * 40 + cc * 8) * 2,  \
                          Wh + (size_t)row * 512 + kw0 + cc * 8);                \
            } else {                                                             \
                int r2 = i - 1280;                                               \
                int row = r2 >> 2, cc = r2 & 3;                                  \
                cpasync16(sb + 51200 + (BUF) * 10240 + (row * 40 + cc * 8) * 2,  \
                          Wl + (size_t)row * 512 + kw0 + cc * 8);                \
            }                                                                    \
        }                                                                        \
    } while (0)

    LOAD_SLAB(0, 0);
    cpcommit();
    cpwait<0>();
    __syncthreads();

    for (int kin = 0; kin < 16; kin++) {
        int cur = kin & 1;
        if (kin + 1 < 16) {
            LOAD_SLAB(kin + 1, cur ^ 1);
            cpcommit();
        }
        uint32_t sAh = sb + cur * 7680;
        uint32_t sAl = sb + 15360 + cur * 7680;
        uint32_t sWh = sb + 30720 + cur * 10240;
        uint32_t sWl = sb + 51200 + cur * 10240;
        #pragma unroll
        for (int pass = 0; pass < 3; pass++) {
            uint32_t sA = (pass == 2) ? sAl : sAh;
            uint32_t sB = (pass == 1) ? sWl : sWh;
            #pragma unroll
            for (int s = 0; s < 2; s++) {
                uint32_t afr[3][4];
                uint32_t bfr[4][2];
                #pragma unroll
                for (int mt = 0; mt < 3; mt++) {
                    uint32_t addrA = sA + ((warpM * 48 + mt * 16 + (lane & 15)) * 40) * 2
                                   + s * 32 + ((lane >> 4) << 4);
                    ldsm_x4(afr[mt][0], afr[mt][1], afr[mt][2], afr[mt][3], addrA);
                }
                #pragma unroll
                for (int nt = 0; nt < 4; nt++) {
                    uint32_t addrB = sB + ((warpN * 32 + nt * 8 + (lane & 7)) * 40) * 2
                                   + s * 32 + (((lane >> 3) & 1) << 4);
                    ldsm_x2(bfr[nt][0], bfr[nt][1], addrB);
                }
                #pragma unroll
                for (int mt = 0; mt < 3; mt++)
                    #pragma unroll
                    for (int nt = 0; nt < 4; nt++)
                        mma16816(acc[mt][nt], afr[mt], bfr[nt]);
            }
        }
        if (kin + 1 < 16) {
            cpwait<0>();
        }
        __syncthreads();
    }
    #undef LOAD_SLAB

    float* sC = (float*)smemf;
    #pragma unroll
    for (int mt = 0; mt < 3; mt++) {
        #pragma unroll
        for (int half = 0; half < 2; half++) {
            int row = warpM * 48 + mt * 16 + (lane >> 2) + half * 8;
            #pragma unroll
            for (int nt = 0; nt < 4; nt++) {
                int col = warpN * 32 + nt * 8 + (lane & 3) * 2;
                sC[row * 133 + col]     = acc[mt][nt][half * 2 + 0];
                sC[row * 133 + col + 1] = acc[mt][nt][half * 2 + 1];
            }
        }
    }
    __syncthreads();

    int b = jBase / 6144;
    int nB = (jBase % 6144) / 3;
    for (int item = tid; item < 12288; item += 256) {
        int g = item & 31;
        int dcol = item >> 5;
        int d = dcol % 3, o = dcol / 3;
        out[big_off + (((size_t)(b * 128 + o)) * 3 + d) * Npts + nB + g]
            = sC[(g * 3 + d) * 133 + o];
    }

    // per-CTA partial sums for the output mean
    for (int w2 = tid; w2 < 384; w2 += 256) {
        int d = w2 % 3, o = w2 / 3;
        float sum = 0.f;
        #pragma unroll 8
        for (int g = 0; g < 32; g++) sum += sC[(g * 3 + d) * 133 + o];
        g_opart[blockIdx.x * 384 + w2] = sum;
    }
}

// ---------------- output-mean reduce ----------------
__global__ void mean_reduce_kernel(float* __restrict__ out, int mean_off) {
    int w = blockIdx.x * 256 + threadIdx.x;
    if (w >= 3072) return;
    int b = w / 384, rem = w % 384;
    float s = 0.f;
    #pragma unroll 8
    for (int chunk = 0; chunk < 64; chunk++)
        s += g_opart[(size_t)(b * 64 + chunk) * 384 + rem];
    out[mean_off + w] = s * (1.f / (float)Npts);
}

// ---------------- mean (from partials) + g-half bias ----------------
__global__ __launch_bounds__(256)
void meanN_bias_kernel(const bf16* __restrict__ GWh, const bf16* __restrict__ GWl) {
    __shared__ float gm[128];
    int bd = blockIdx.x;
    int b = bd / 3, d = bd % 3;
    if (threadIdx.x < 128) {
        int c = threadIdx.x;
        float t = 0.f;
        #pragma unroll 8
        for (int chunk = 0; chunk < 64; chunk++)
            t += g_pmean[(size_t)(b * 64 + chunk) * 384 + d * 128 + c];
        g_gmean[bd * Hc + c] = t;
        gm[c] = t * (1.f / (float)Npts);
    }
    __syncthreads();
    {
        int o = threadIdx.x;
        const bf16* rh = GWh + (size_t)o * 256 + 128;
        const bf16* rl = GWl + (size_t)o * 256 + 128;
        float acc = 0.f;
        #pragma unroll 8
        for (int cc = 0; cc < 128; cc++)
            acc += (__bfloat162float(rh[cc]) + __bfloat162float(rl[cc])) * gm[cc];
        g_bias[bd * 256 + o] = acc;
    }
}

// ---------------- host launcher ----------------
extern "C" void kernel_launch(void* const* d_in, const int* in_sizes, int n_in,
                              void* d_out, int out_size) {
    const float* x     = (const float*)d_in[0];
    const float* W_in  = (const float*)d_in[1];
    const float* Wd_in = (const float*)d_in[2];
    const float* Ws    = (const float*)d_in[3];
    const float* Wds   = (const float*)d_in[4];
    const float* Gs    = (const float*)d_in[5];
    const float* Gds   = (const float*)d_in[6];
    const float* W_out = (const float*)d_in[7];
    float* out = (float*)d_out;

    float *pBias, *pPmean;
    bf16 *pX0h, *pX0l, *pX2h, *pX2l, *pFTh, *pFTl, *pUKh, *pUKl, *pGWh, *pGWl, *pOWh, *pOWl;
    cudaGetSymbolAddress((void**)&pBias, g_bias);
    cudaGetSymbolAddress((void**)&pPmean, g_pmean);
    cudaGetSymbolAddress((void**)&pX0h, g_X0h);
    cudaGetSymbolAddress((void**)&pX0l, g_X0l);
    cudaGetSymbolAddress((void**)&pX2h, g_X2h);
    cudaGetSymbolAddress((void**)&pX2l, g_X2l);
    cudaGetSymbolAddress((void**)&pFTh, g_FTh);
    cudaGetSymbolAddress((void**)&pFTl, g_FTl);
    cudaGetSymbolAddress((void**)&pUKh, g_UKh);
    cudaGetSymbolAddress((void**)&pUKl, g_UKl);
    cudaGetSymbolAddress((void**)&pGWh, g_GWh);
    cudaGetSymbolAddress((void**)&pGWl, g_GWl);
    cudaGetSymbolAddress((void**)&pOWh, g_OWh);
    cudaGetSymbolAddress((void**)&pOWl, g_OWl);

    cudaFuncSetAttribute(gemm_pw, cudaFuncAttributeMaxDynamicSharedMemorySize, PW_SMEM);
    cudaFuncSetAttribute(gemm_final, cudaFuncAttributeMaxDynamicSharedMemorySize, GF_SMEM);

    int mean_off = 0, big_off = 0;
    bool has_mean = true;
    const int BIG = Bsz * CDc * 3 * Npts;
    const int MEAN = Bsz * CDc * 3;
    if (out_size >= BIG + MEAN) { mean_off = 0; big_off = MEAN; }
    else { big_off = 0; has_mean = false; }

    const int prepTot = 384 + 9 + Lc * 256 * 128 + Lc * 256 * 256 + 128 * 512;
    prep_kernel<<<(prepTot + 255) / 256, 256>>>(W_in, Wd_in, Ws, Wds, Gs, Gds, W_out);
    knn_kernel<<<Bsz * 16, 128>>>(x);
    stage2_kernel<<<NBlk, 128>>>(x, W_in);

    const bf16* Xh = pX0h;
    const bf16* Xl = pX0l;
    const int pwGrid = Jtot / 96;                  // 512
    for (int i = 0; i < Lc; i++) {
        gemm_pw<<<pwGrid, 512, PW_SMEM>>>(Xh, Xl,
                    pUKh + (size_t)i * 256 * 128, pUKl + (size_t)i * 256 * 128, 128,
                    nullptr, pX2h, pX2l, 128, 0, pPmean);
        meanN_bias_kernel<<<24, 256>>>(pGWh + (size_t)i * 256 * 256,
                                       pGWl + (size_t)i * 256 * 256);
        gemm_pw<<<pwGrid, 512, PW_SMEM>>>(pX2h, pX2l,
                    pGWh + (size_t)i * 256 * 256, pGWl + (size_t)i * 256 * 256, 256,
                    pBias, pFTh + (size_t)i * FSEG, pFTl + (size_t)i * FSEG, 128, 0,
                    nullptr);
        Xh = pFTh + (size_t)i * FSEG;
        Xl = pFTl + (size_t)i * FSEG;
    }
    gemm_final<<<Jtot / 96, 256, GF_SMEM>>>(pFTh, pFTl, pOWh, pOWl, out, big_off);
    if (has_mean) mean_reduce_kernel<<<12, 256>>>(out, mean_off);
}